// round 13
// baseline (speedup 1.0000x reference)
#include <cuda_runtime.h>
#include <cuda_fp16.h>
#include <cstdint>

#define Bsz 32
#define Ssz 2048
#define BS (Bsz*Ssz)   // 65536 rows
#define WIN 44         // attention smem window rows (32 + 2*6 halo)

// ---------------- scratch (device globals; no allocation) ----------------
__device__ __half g_qk0[(size_t)BS*256];
__device__ __half g_qk1[(size_t)BS*256];
__device__ __half g_v  [(size_t)BS*256];
__device__ __half g_hq [(size_t)BS*256];
__device__ __half g_hs [(size_t)BS*256];
__device__ __half g_ath0[(size_t)BS*256];
__device__ __half g_wlh[3*2*128*128];
__device__ __half g_woh[3*256*256];

// ================= helpers =================
__device__ __forceinline__ uint32_t smem_u32(const void* p) {
    uint32_t a;
    asm("{ .reg .u64 t; cvta.to.shared.u64 t, %1; cvt.u32.u64 %0, t; }"
        : "=r"(a) : "l"(p));
    return a;
}
__device__ __forceinline__ void ldsm4(uint32_t r[4], uint32_t addr) {
    asm volatile("ldmatrix.sync.aligned.m8n8.x4.shared.b16 {%0,%1,%2,%3}, [%4];"
                 : "=r"(r[0]), "=r"(r[1]), "=r"(r[2]), "=r"(r[3]) : "r"(addr));
}
__device__ __forceinline__ void mma_f16(float4& c, const uint32_t a[4],
                                        uint32_t b0, uint32_t b1) {
    asm volatile(
        "mma.sync.aligned.m16n8k16.row.col.f32.f16.f16.f32 "
        "{%0,%1,%2,%3}, {%4,%5,%6,%7}, {%8,%9}, {%0,%1,%2,%3};"
        : "+f"(c.x), "+f"(c.y), "+f"(c.z), "+f"(c.w)
        : "r"(a[0]), "r"(a[1]), "r"(a[2]), "r"(a[3]), "r"(b0), "r"(b1));
}
__device__ __forceinline__ void cp16(uint32_t dst, const void* src) {
    asm volatile("cp.async.cg.shared.global [%0], [%1], 16;"
                 :: "r"(dst), "l"(src) : "memory");
}

// Fill a 64-row x 64-col chunk into fp16 smem (row stride 72 halves), 256 threads.
__device__ __forceinline__ void fill_hi64(const float* __restrict__ src, int stride,
                                          uint32_t* __restrict__ hi, int tid) {
    #pragma unroll
    for (int it = 0; it < 8; it++) {
        int idx = tid + it * 256;
        int row = idx >> 5, c2 = idx & 31;
        float2 v = *(const float2*)(src + (size_t)row * stride + c2 * 2);
        __half2 h = __floats2half2_rn(v.x, v.y);
        hi[row * 36 + c2] = *reinterpret_cast<uint32_t*>(&h);
    }
}
__device__ __forceinline__ void fill_hi64(const __half* __restrict__ src, int stride,
                                          uint32_t* __restrict__ hi, int tid) {
    #pragma unroll
    for (int it = 0; it < 8; it++) {
        int idx = tid + it * 256;
        int row = idx >> 5, c2 = idx & 31;
        hi[row * 36 + c2] = *(const uint32_t*)(src + (size_t)row * stride + c2 * 2);
    }
}
__device__ __forceinline__ float2 ld2f(const float* p) { return *(const float2*)p; }
__device__ __forceinline__ float2 ld2f(const __half* p) {
    uint32_t r = *(const uint32_t*)p;
    __half2 h = *reinterpret_cast<__half2*>(&r);
    return make_float2(__low2float(h), __high2float(h));
}
__device__ __forceinline__ void st2f(float* p, float2 v) { *(float2*)p = v; }
__device__ __forceinline__ void st2f(__half* p, float2 v) {
    __half2 h = __floats2half2_rn(v.x, v.y);
    *(uint32_t*)p = *reinterpret_cast<uint32_t*>(&h);
}

// ================= weight fp16 prep =================
__global__ void split_w(const float* __restrict__ Wl, const float* __restrict__ Wo,
                        __half* __restrict__ wlh, __half* __restrict__ woh)
{
    int i = blockIdx.x * 256 + threadIdx.x;
    if (i < 3*2*128*128) wlh[i] = __float2half_rn(Wl[i]);
    if (i < 3*256*256)   woh[i] = __float2half_rn(Wo[i]);
}

// ================= projection GEMM (64-row tile, 256 thr, 2 CTA/SM) =================
#define PR_BIAS 33792u
#define PR_SMEM 34304u

template<typename TIN>
__global__ __launch_bounds__(256) void proj_mma(
    const TIN* __restrict__ x0, const TIN* __restrict__ x1,
    const __half* __restrict__ whi, int wstep,
    const float* __restrict__ bias, int bstep,
    __half* __restrict__ out0, __half* __restrict__ out1)
{
    extern __shared__ __align__(16) char sm[];
    uint32_t* Ahi = (uint32_t*)(sm);
    char* Bhi = sm + 9216;
    float* sbias  = (float*)(sm + PR_BIAS);
    float* stg    = (float*)sm;

    const int chain = blockIdx.z;
    const TIN* x = chain ? x1 : x0;
    __half* out = chain ? out1 : out0;
    const int branch = blockIdx.y;
    const int r0 = blockIdx.x * 64;
    const int tid = threadIdx.x, lane = tid & 31, wid = tid >> 5;
    const int m0 = (wid >> 2) * 32, n0 = (wid & 3) * 32;

    const float* bp = bias + chain * bstep + branch * 128;
    if (tid < 128) sbias[tid] = bp[tid];

    const uint32_t sA = smem_u32(Ahi), sB = smem_u32(Bhi);
    const int a_row = lane & 15, a_kh = (lane >> 4) << 3;
    const int b_n = (lane & 7) + ((lane >> 4) << 3);
    const int b_kh = ((lane >> 3) & 1) << 3;

    float4 acc[2][4];
    #pragma unroll
    for (int i = 0; i < 2; i++)
        #pragma unroll
        for (int j = 0; j < 4; j++) acc[i][j] = make_float4(0.f, 0.f, 0.f, 0.f);

    const TIN* xp = x + (size_t)r0 * 256 + branch * 128;
    const __half* whb = whi + (size_t)chain * wstep + (size_t)branch * 128 * 128;

    uint32_t aAddr[2], bAddr[2];
    aAddr[0] = sA + ((m0 + a_row) * 72 + a_kh) * 2;
    aAddr[1] = sA + ((m0 + 16 + a_row) * 72 + a_kh) * 2;
    bAddr[0] = sB + ((n0 + b_n) * 72 + b_kh) * 2;
    bAddr[1] = sB + ((n0 + 16 + b_n) * 72 + b_kh) * 2;

    for (int kc = 0; kc < 128; kc += 64) {
        fill_hi64(xp + kc, 256, Ahi, tid);
        #pragma unroll
        for (int it = 0; it < 4; it++) {
            int idx = tid + it * 256;
            int row = idx >> 3, u = idx & 7;
            *(uint4*)(Bhi + row * 144 + u * 16) =
                *(const uint4*)(whb + row * 128 + kc + u * 8);
        }
        __syncthreads();
        #pragma unroll
        for (int ks = 0; ks < 4; ks++) {
            uint32_t ah[2][4], bh[2][4];
            #pragma unroll
            for (int mt = 0; mt < 2; mt++) ldsm4(ah[mt], aAddr[mt] + ks * 32);
            #pragma unroll
            for (int bt = 0; bt < 2; bt++) ldsm4(bh[bt], bAddr[bt] + ks * 32);
            #pragma unroll
            for (int mt = 0; mt < 2; mt++)
                #pragma unroll
                for (int bt = 0; bt < 2; bt++)
                    #pragma unroll
                    for (int sub = 0; sub < 2; sub++)
                        mma_f16(acc[mt][bt * 2 + sub], ah[mt],
                                bh[bt][sub*2], bh[bt][sub*2+1]);
        }
        __syncthreads();
    }

    #pragma unroll
    for (int mt = 0; mt < 2; mt++) {
        int rb = m0 + mt * 16 + (lane >> 2);
        #pragma unroll
        for (int nt = 0; nt < 4; nt++) {
            int j = n0 + nt * 8 + (lane & 3) * 2;
            int p0 = ((j & 31) << 2) + (j >> 5);
            int p1 = (((j + 1) & 31) << 2) + ((j + 1) >> 5);
            float4 a = acc[mt][nt];
            stg[rb * 132 + p0]       = a.x + sbias[j];
            stg[rb * 132 + p1]       = a.y + sbias[j + 1];
            stg[(rb + 8) * 132 + p0] = a.z + sbias[j];
            stg[(rb + 8) * 132 + p1] = a.w + sbias[j + 1];
        }
    }
    __syncthreads();
    #pragma unroll
    for (int it = 0; it < 8; it++) {
        int idx = tid + it * 256;
        int row = idx >> 5, q = idx & 31;
        float4 v = *(const float4*)(stg + row * 132 + q * 4);
        __half2 h0 = __floats2half2_rn(v.x, v.y);
        __half2 h1 = __floats2half2_rn(v.z, v.w);
        uint2 u = make_uint2(*reinterpret_cast<uint32_t*>(&h0),
                             *reinterpret_cast<uint32_t*>(&h1));
        *(uint2*)(out + (size_t)(r0 + row) * 256 + branch * 128 + q * 4) = u;
    }
}

// ================= FUSED attention + out-proj + residual + LN (blocks 1&2) =================
// 32 output rows/CTA + 12-row halo; QK==V. smem: qk window (skewed fp16 pairs),
// A in ldmatrix layout, single W buffer (cp.async), LN scratch. 80256 B -> 2 CTA/SM.
#define FA_QK   0u
#define FA_A    23936u      // 44*136*4
#define FA_W    42368u      // +4*4608
#define FA_SUM  79232u      // +36864
#define FA_SQ   79744u
#define FA_SMEM 80256u

__global__ __launch_bounds__(256) void fused_ao(
    const __half* __restrict__ qk0, const __half* __restrict__ qk1,
    const __half* __restrict__ Whi, int wstep,
    const float* __restrict__ bo, const float* __restrict__ xr0,
    const float* __restrict__ xr1,
    const float* __restrict__ g, const float* __restrict__ bb, int pstep,
    __half* __restrict__ out0, __half* __restrict__ out1,
    float* __restrict__ qs)
{
    extern __shared__ __align__(16) char sm[];
    const int chain = blockIdx.y;
    const __half* QK = chain ? qk1 : qk0;
    const __half* Wp = Whi + (size_t)chain * wstep;
    const float* xres = chain ? xr1 : xr0;
    const float* bop = bo + chain * pstep;
    const float* gp  = g  + chain * pstep;
    const float* bbp = bb + chain * pstep;
    __half* out = chain ? out1 : out0;

    const int r0 = blockIdx.x * 32;
    const int b = r0 >> 11, s0 = r0 & 2047;
    const int tid = threadIdx.x, lane = tid & 31, wid = tid >> 5;
    const int m0 = (wid >> 2) * 16, n0 = (wid & 3) * 64;
    const uint32_t sb = smem_u32(sm);
    uint32_t* sQK32 = (uint32_t*)sm;
    uint16_t* Asm = (uint16_t*)(sm + FA_A);
    const uint32_t sA = sb + FA_A, sW = sb + FA_W;

    auto loadW = [&](int kc) {
        #pragma unroll
        for (int it = 0; it < 8; it++) {          // 256 rows x 8 quads = 2048 cp16
            int idx = tid + it * 256;
            int row = idx >> 3, u = idx & 7;
            cp16(sW + row * 144 + u * 16, Wp + (size_t)row * 256 + kc * 64 + u * 8);
        }
        asm volatile("cp.async.commit_group;" ::: "memory");
    };
    loadW(0);   // hides under attention phase

    // L2 prefetch of the residual tile (consumed in epilogue)
    {
        const float* pf = xres + (size_t)(r0 + (tid >> 3)) * 256 + (tid & 7) * 32;
        asm volatile("prefetch.global.L2 [%0];" :: "l"(pf));
    }

    // qk window: 44 rows x 128 fp16-pairs, skewed (row stride 136 u32, head stride 17)
    for (int idx = tid; idx < 44 * 128; idx += 256) {
        int w = idx >> 7, p = idx & 127;
        int s = s0 + w - 6;
        uint32_t v = 0;
        if (s >= 0 && s < Ssz)
            v = ((const uint32_t*)QK)[((size_t)b * Ssz + s) * 128 + p];
        sQK32[w * 136 + (p >> 4) * 17 + (p & 15)] = v;
    }
    __syncthreads();

    // ---- attention: 1 task per thread (32 rows x 8 heads) ----
    {
        const int sl = tid >> 3, h = tid & 7;
        const int dil = (h < 4) ? 3 : 1;
        const float scale = 0.1767766952966369f;
        const uint32_t* qp = sQK32 + (sl + 6) * 136 + h * 17;

        float qv[32];
        #pragma unroll
        for (int j = 0; j < 16; j++) {
            __half2 hh = *(const __half2*)(qp + j);
            qv[2*j] = __low2float(hh); qv[2*j+1] = __high2float(hh);
        }
        float sc[5];
        #pragma unroll
        for (int k = 0; k < 5; k++) {
            const uint32_t* kp = sQK32 + (sl + 6 + (k - 2) * dil) * 136 + h * 17;
            float d = 0.f;
            #pragma unroll
            for (int j = 0; j < 16; j++) {
                __half2 kh = *(const __half2*)(kp + j);
                d += qv[2*j] * __low2float(kh) + qv[2*j+1] * __high2float(kh);
            }
            sc[k] = d * scale;
        }
        float mx = sc[0];
        #pragma unroll
        for (int k = 1; k < 5; k++) mx = fmaxf(mx, sc[k]);
        float ex[5], sum = 0.f;
        #pragma unroll
        for (int k = 0; k < 5; k++) { ex[k] = __expf(sc[k] - mx); sum += ex[k]; }
        float inv = 1.f / sum;
        #pragma unroll
        for (int k = 0; k < 5; k++) ex[k] *= inv;

        // output -> A smem (ldmatrix layout; chunk = h>>1, half = h&1)
        const uint32_t* v0 = sQK32 + (sl + 6 - 2 * dil) * 136 + h * 17;
        const int vstep = dil * 136;
        int aoff = (h >> 1) * 2304 + sl * 72 + (h & 1) * 32;  // halves
        #pragma unroll
        for (int j = 0; j < 16; j++) {
            float ox = 0.f, oy = 0.f;
            #pragma unroll
            for (int k = 0; k < 5; k++) {
                __half2 vh = *(const __half2*)(v0 + k * vstep + j);
                ox += ex[k] * __low2float(vh);
                oy += ex[k] * __high2float(vh);
            }
            __half2 oh = __floats2half2_rn(ox, oy);
            *(uint32_t*)(Asm + aoff + 2 * j) = *reinterpret_cast<uint32_t*>(&oh);
        }

        if (chain) {
            float* sp = qs + (((size_t)b * 8 + h) * Ssz + s0 + sl) * 5;
            #pragma unroll
            for (int k = 0; k < 5; k++) sp[k] = ex[k];
        }
    }
    asm volatile("cp.async.wait_group 0;" ::: "memory");
    __syncthreads();

    // ---- GEMM: 32x256, K=256 in 4 chunks; A resident, W single-buffered ----
    const int a_row = lane & 15, a_kh = (lane >> 4) << 3;
    const int b_n = (lane & 7) + ((lane >> 4) << 3);
    const int b_kh = ((lane >> 3) & 1) << 3;
    const uint32_t aOffBase = ((m0 + a_row) * 72 + a_kh) * 2;
    const uint32_t bAddr = sW + ((n0 + b_n) * 72 + b_kh) * 2;

    float4 acc[8];
    #pragma unroll
    for (int j = 0; j < 8; j++) acc[j] = make_float4(0.f, 0.f, 0.f, 0.f);

    #pragma unroll 1
    for (int kc = 0; kc < 4; kc++) {
        uint32_t aB = sA + kc * 4608 + aOffBase;
        #pragma unroll
        for (int ks = 0; ks < 4; ks++) {
            uint32_t ah[4];
            ldsm4(ah, aB + ks * 32);
            #pragma unroll
            for (int nb = 0; nb < 4; nb++) {
                uint32_t bh[4];
                ldsm4(bh, bAddr + nb * 2304 + ks * 32);
                mma_f16(acc[nb * 2],     ah, bh[0], bh[1]);
                mma_f16(acc[nb * 2 + 1], ah, bh[2], bh[3]);
            }
        }
        __syncthreads();
        if (kc < 3) {
            loadW(kc + 1);
            asm volatile("cp.async.wait_group 0;" ::: "memory");
            __syncthreads();
        }
    }

    // ---- epilogue: bias + residual + LN ----
    float sums[2] = {0.f, 0.f}, sqs2[2] = {0.f, 0.f};
    const int rl = r0 + m0 + (lane >> 2);
    #pragma unroll
    for (int nt = 0; nt < 8; nt++) {
        int c = n0 + nt * 8 + (lane & 3) * 2;
        float2 bo2 = *(const float2*)(bop + c);
        float2 xl = *(const float2*)(xres + (size_t)rl * 256 + c);
        float2 xh = *(const float2*)(xres + (size_t)(rl + 8) * 256 + c);
        float4& a = acc[nt];
        a.x += bo2.x + xl.x; a.y += bo2.y + xl.y;
        a.z += bo2.x + xh.x; a.w += bo2.y + xh.y;
        sums[0] += a.x + a.y; sqs2[0] += a.x*a.x + a.y*a.y;
        sums[1] += a.z + a.w; sqs2[1] += a.z*a.z + a.w*a.w;
    }
    #pragma unroll
    for (int hf = 0; hf < 2; hf++) {
        sums[hf] += __shfl_xor_sync(0xffffffffu, sums[hf], 1);
        sums[hf] += __shfl_xor_sync(0xffffffffu, sums[hf], 2);
        sqs2[hf] += __shfl_xor_sync(0xffffffffu, sqs2[hf], 1);
        sqs2[hf] += __shfl_xor_sync(0xffffffffu, sqs2[hf], 2);
    }
    float* ssum = (float*)(sm + FA_SUM);
    float* ssq  = (float*)(sm + FA_SQ);
    if ((lane & 3) == 0) {
        #pragma unroll
        for (int hf = 0; hf < 2; hf++) {
            int row = m0 + hf * 8 + (lane >> 2);
            ssum[(wid & 3) * 32 + row] = sums[hf];
            ssq [(wid & 3) * 32 + row] = sqs2[hf];
        }
    }
    __syncthreads();
    float mu[2], rs[2];
    #pragma unroll
    for (int hf = 0; hf < 2; hf++) {
        int row = m0 + hf * 8 + (lane >> 2);
        float s = ssum[row] + ssum[32 + row] + ssum[64 + row] + ssum[96 + row];
        float q = ssq[row] + ssq[32 + row] + ssq[64 + row] + ssq[96 + row];
        float m = s * (1.f / 256.f);
        mu[hf] = m;
        rs[hf] = rsqrtf(q * (1.f / 256.f) - m * m + 1e-5f);
    }
    #pragma unroll
    for (int nt = 0; nt < 8; nt++) {
        int c = n0 + nt * 8 + (lane & 3) * 2;
        float2 g2 = *(const float2*)(gp + c);
        float2 b2 = *(const float2*)(bbp + c);
        float4 a = acc[nt];
        float2 o1, o2;
        o1.x = (a.x - mu[0]) * rs[0] * g2.x + b2.x;
        o1.y = (a.y - mu[0]) * rs[0] * g2.y + b2.y;
        o2.x = (a.z - mu[1]) * rs[1] * g2.x + b2.x;
        o2.y = (a.w - mu[1]) * rs[1] * g2.y + b2.y;
        st2f(out + (size_t)rl * 256 + c, o1);
        st2f(out + (size_t)(rl + 8) * 256 + c, o2);
    }
}

// ================= out-proj + residual + LN for block 3 (unchanged path) =================
#define OLS_STAGE 46080u
#define OLS_SUM   92160u
#define OLS_SQ    93184u
#define OLS_SMEM  94208u

__global__ __launch_bounds__(256) void outln_b3(
    const __half* __restrict__ Ahi,
    const __half* __restrict__ Wp,
    const float* __restrict__ bop, const __half* __restrict__ xres,
    const float* __restrict__ gp, const float* __restrict__ bbp,
    float* __restrict__ out)
{
    extern __shared__ __align__(16) char sm[];
    const int r0 = blockIdx.x * 64;
    const int tid = threadIdx.x, lane = tid & 31, wid = tid >> 5;
    const int m0 = (wid >> 2) * 32, n0 = (wid & 3) * 64;
    const uint32_t sb = smem_u32(sm);

    auto load_chunk = [&](int kc) {
        uint32_t st = sb + (uint32_t)(kc & 1) * OLS_STAGE;
        const __half* ah = Ahi + (size_t)r0 * 256 + kc * 64;
        const __half* wh = Wp + kc * 64;
        #pragma unroll
        for (int it = 0; it < 2; it++) {
            int idx = tid + it * 256;
            int row = idx >> 3, u = idx & 7;
            cp16(st + row * 144 + u * 16, ah + (size_t)row * 256 + u * 8);
        }
        #pragma unroll
        for (int it = 0; it < 8; it++) {
            int idx = tid + it * 256;
            int row = idx >> 3, u = idx & 7;
            cp16(st + 9216u + row * 144 + u * 16, wh + (size_t)row * 256 + u * 8);
        }
        asm volatile("cp.async.commit_group;" ::: "memory");
    };

    const int a_row = lane & 15, a_kh = (lane >> 4) << 3;
    const int b_n = (lane & 7) + ((lane >> 4) << 3);
    const int b_kh = ((lane >> 3) & 1) << 3;
    const uint32_t aOff = ((m0 + a_row) * 72 + a_kh) * 2;
    const uint32_t bOff = 9216u + ((n0 + b_n) * 72 + b_kh) * 2;

    float4 acc[2][8];
    #pragma unroll
    for (int i = 0; i < 2; i++)
        #pragma unroll
        for (int j = 0; j < 8; j++) acc[i][j] = make_float4(0.f, 0.f, 0.f, 0.f);

    load_chunk(0);
    #pragma unroll 1
    for (int kc = 0; kc < 4; kc++) {
        if (kc < 3) {
            load_chunk(kc + 1);
            asm volatile("cp.async.wait_group 1;" ::: "memory");
        } else {
            asm volatile("cp.async.wait_group 0;" ::: "memory");
        }
        __syncthreads();
        uint32_t st = sb + (uint32_t)(kc & 1) * OLS_STAGE;
        uint32_t aB = st + aOff, bB = st + bOff;
        #pragma unroll
        for (int ks = 0; ks < 4; ks++) {
            uint32_t ah[2][4];
            ldsm4(ah[0], aB + ks * 32);
            ldsm4(ah[1], aB + 2304 + ks * 32);
            #pragma unroll
            for (int nb = 0; nb < 4; nb++) {
                uint32_t bh[4];
                ldsm4(bh, bB + nb * 2304 + ks * 32);
                #pragma unroll
                for (int mt = 0; mt < 2; mt++)
                    #pragma unroll
                    for (int sub = 0; sub < 2; sub++)
                        mma_f16(acc[mt][nb * 2 + sub], ah[mt],
                                bh[sub*2], bh[sub*2+1]);
            }
        }
        __syncthreads();
    }

    float sums[2][2] = {{0.f,0.f},{0.f,0.f}}, sqs[2][2] = {{0.f,0.f},{0.f,0.f}};
    #pragma unroll
    for (int mt = 0; mt < 2; mt++) {
        int rl = r0 + m0 + mt * 16 + (lane >> 2);
        #pragma unroll
        for (int nt = 0; nt < 8; nt++) {
            int c = n0 + nt * 8 + (lane & 3) * 2;
            float2 bo2 = *(const float2*)(bop + c);
            float2 xl = ld2f(xres + (size_t)rl * 256 + c);
            float2 xh = ld2f(xres + (size_t)(rl + 8) * 256 + c);
            float4& a = acc[mt][nt];
            a.x += bo2.x + xl.x; a.y += bo2.y + xl.y;
            a.z += bo2.x + xh.x; a.w += bo2.y + xh.y;
            sums[mt][0] += a.x + a.y; sqs[mt][0] += a.x*a.x + a.y*a.y;
            sums[mt][1] += a.z + a.w; sqs[mt][1] += a.z*a.z + a.w*a.w;
        }
    }
    #pragma unroll
    for (int mt = 0; mt < 2; mt++)
        #pragma unroll
        for (int hf = 0; hf < 2; hf++) {
            sums[mt][hf] += __shfl_xor_sync(0xffffffffu, sums[mt][hf], 1);
            sums[mt][hf] += __shfl_xor_sync(0xffffffffu, sums[mt][hf], 2);
            sqs[mt][hf]  += __shfl_xor_sync(0xffffffffu, sqs[mt][hf], 1);
            sqs[mt][hf]  += __shfl_xor_sync(0xffffffffu, sqs[mt][hf], 2);
        }
    float* ssum = (float*)(sm + OLS_SUM);
    float* ssq  = (float*)(sm + OLS_SQ);
    if ((lane & 3) == 0) {
        #pragma unroll
        for (int mt = 0; mt < 2; mt++)
            #pragma unroll
            for (int hf = 0; hf < 2; hf++) {
                int row = m0 + mt * 16 + hf * 8 + (lane >> 2);
                ssum[(wid & 3) * 64 + row] = sums[mt][hf];
                ssq [(wid & 3) * 64 + row] = sqs[mt][hf];
            }
    }
    __syncthreads();
    float mu[2][2], rs[2][2];
    #pragma unroll
    for (int mt = 0; mt < 2; mt++)
        #pragma unroll
        for (int hf = 0; hf < 2; hf++) {
            int row = m0 + mt * 16 + hf * 8 + (lane >> 2);
            float s = ssum[row] + ssum[64 + row] + ssum[128 + row] + ssum[192 + row];
            float q = ssq[row] + ssq[64 + row] + ssq[128 + row] + ssq[192 + row];
            float m = s * (1.f / 256.f);
            mu[mt][hf] = m;
            rs[mt][hf] = rsqrtf(q * (1.f / 256.f) - m * m + 1e-5f);
        }
    #pragma unroll
    for (int mt = 0; mt < 2; mt++) {
        int rl = r0 + m0 + mt * 16 + (lane >> 2);
        #pragma unroll
        for (int nt = 0; nt < 8; nt++) {
            int c = n0 + nt * 8 + (lane & 3) * 2;
            float2 g2 = *(const float2*)(gp + c);
            float2 b2 = *(const float2*)(bbp + c);
            float4 a = acc[mt][nt];
            float2 o1, o2;
            o1.x = (a.x - mu[mt][0]) * rs[mt][0] * g2.x + b2.x;
            o1.y = (a.y - mu[mt][0]) * rs[mt][0] * g2.y + b2.y;
            o2.x = (a.z - mu[mt][1]) * rs[mt][1] * g2.x + b2.x;
            o2.y = (a.w - mu[mt][1]) * rs[mt][1] * g2.y + b2.y;
            st2f(out + (size_t)rl * 256 + c, o1);
            st2f(out + (size_t)(rl + 8) * 256 + c, o2);
        }
    }
}

// ================= attention for block 3 (QK != V), fp32 smem path =================
#define ATT_STRIDE 288
#define ATT2_SMEM (2 * WIN * ATT_STRIDE * 4)   // 101376

__device__ __forceinline__ float4 h4_to_f4(uint2 raw) {
    __half2 h0 = *reinterpret_cast<__half2*>(&raw.x);
    __half2 h1 = *reinterpret_cast<__half2*>(&raw.y);
    return make_float4(__low2float(h0), __high2float(h0),
                       __low2float(h1), __high2float(h1));
}

__global__ __launch_bounds__(256) void attn_two(
    const __half* __restrict__ QK, const __half* __restrict__ V,
    __half* __restrict__ ath)
{
    extern __shared__ float smf[];
    float* sQK = smf;
    float* sV  = smf + WIN * ATT_STRIDE;
    const int b  = blockIdx.y;
    const int s0 = blockIdx.x * 32;
    const int tid = threadIdx.x;

    for (int idx = tid; idx < WIN * 64; idx += 256) {
        int w = idx >> 6, c4 = idx & 63;
        int s = s0 + w - 6;
        float4 vq = make_float4(0.f, 0.f, 0.f, 0.f);
        float4 vv = vq;
        if (s >= 0 && s < Ssz) {
            size_t off = ((size_t)b * Ssz + s) * 64 + c4;
            vq = h4_to_f4(((const uint2*)QK)[off]);
            vv = h4_to_f4(((const uint2*)V)[off]);
        }
        int sc = w * ATT_STRIDE + (c4 >> 3) * 36 + (c4 & 7) * 4;
        *(float4*)(sQK + sc) = vq;
        *(float4*)(sV + sc)  = vv;
    }
    __syncthreads();

    const int sl = tid >> 3, h = tid & 7;
    const int dil = (h < 4) ? 3 : 1;
    const float scale = 0.1767766952966369f;
    const int colb = h * 36;

    float4 q[8];
    {
        const float* qr = sQK + (sl + 6) * ATT_STRIDE + colb;
        #pragma unroll
        for (int j = 0; j < 8; j++) q[j] = *(const float4*)(qr + j * 4);
    }
    float sc[5];
    #pragma unroll
    for (int k = 0; k < 5; k++) {
        const float* kr = sQK + (sl + 6 + (k - 2) * dil) * ATT_STRIDE + colb;
        float d = 0.f;
        #pragma unroll
        for (int j = 0; j < 8; j++) {
            float4 kv = *(const float4*)(kr + j * 4);
            d += q[j].x * kv.x + q[j].y * kv.y + q[j].z * kv.z + q[j].w * kv.w;
        }
        sc[k] = d * scale;
    }
    float mx = sc[0];
    #pragma unroll
    for (int k = 1; k < 5; k++) mx = fmaxf(mx, sc[k]);
    float ex[5], sum = 0.f;
    #pragma unroll
    for (int k = 0; k < 5; k++) { ex[k] = __expf(sc[k] - mx); sum += ex[k]; }
    float inv = 1.f / sum;
    #pragma unroll
    for (int k = 0; k < 5; k++) ex[k] *= inv;

    size_t base = ((size_t)b * Ssz + s0 + sl) * 256 + h * 32;
    const float* v0 = sV + (sl + 6 - 2 * dil) * ATT_STRIDE + colb;
    const int vstep = dil * ATT_STRIDE;
    uint32_t Hw[16];
    #pragma unroll
    for (int j = 0; j < 8; j++) {
        float4 o = make_float4(0.f, 0.f, 0.f, 0.f);
        #pragma unroll
        for (int k = 0; k < 5; k++) {
            float4 vv = *(const float4*)(v0 + k * vstep + j * 4);
            o.x += ex[k] * vv.x; o.y += ex[k] * vv.y;
            o.z += ex[k] * vv.z; o.w += ex[k] * vv.w;
        }
        __half2 h0 = __floats2half2_rn(o.x, o.y);
        __half2 h1 = __floats2half2_rn(o.z, o.w);
        Hw[2*j]   = *reinterpret_cast<uint32_t*>(&h0);
        Hw[2*j+1] = *reinterpret_cast<uint32_t*>(&h1);
    }
    #pragma unroll
    for (int u = 0; u < 4; u++) {
        uint4 vh = make_uint4(Hw[u*4], Hw[u*4+1], Hw[u*4+2], Hw[u*4+3]);
        *(uint4*)((char*)(ath + base) + u * 16) = vh;
    }
}

// ================= launch =================
extern "C" void kernel_launch(void* const* d_in, const int* in_sizes, int n_in,
                              void* d_out, int out_size)
{
    (void)in_sizes; (void)n_in; (void)out_size;
    const float* q_emb = (const float*)d_in[0];
    const float* s_emb = (const float*)d_in[1];
    const float* W_lin = (const float*)d_in[3];
    const float* b_lin = (const float*)d_in[4];
    const float* W_out = (const float*)d_in[5];
    const float* b_out = (const float*)d_in[6];
    const float* ln_g  = (const float*)d_in[7];
    const float* ln_b  = (const float*)d_in[8];

    float* outp = (float*)d_out;
    float* z  = outp;
    float* qs = outp + (size_t)BS * 256;

    __half *p_qk0, *p_qk1, *p_v, *p_hq, *p_hs, *p_ath0, *p_wlh, *p_woh;
    cudaGetSymbolAddress((void**)&p_qk0, g_qk0);
    cudaGetSymbolAddress((void**)&p_qk1, g_qk1);
    cudaGetSymbolAddress((void**)&p_v,   g_v);
    cudaGetSymbolAddress((void**)&p_hq,  g_hq);
    cudaGetSymbolAddress((void**)&p_hs,  g_hs);
    cudaGetSymbolAddress((void**)&p_ath0, g_ath0);
    cudaGetSymbolAddress((void**)&p_wlh, g_wlh);
    cudaGetSymbolAddress((void**)&p_woh, g_woh);

    const int smemP  = (int)PR_SMEM;
    const int smemF  = (int)FA_SMEM;    // 80256
    const int smemO  = (int)OLS_SMEM;
    const int smemA2 = ATT2_SMEM;
    cudaFuncSetAttribute(proj_mma<float>,  cudaFuncAttributeMaxDynamicSharedMemorySize, smemP);
    cudaFuncSetAttribute(proj_mma<__half>, cudaFuncAttributeMaxDynamicSharedMemorySize, smemP);
    cudaFuncSetAttribute(fused_ao, cudaFuncAttributeMaxDynamicSharedMemorySize, smemF);
    cudaFuncSetAttribute(outln_b3, cudaFuncAttributeMaxDynamicSharedMemorySize, smemO);
    cudaFuncSetAttribute(attn_two, cudaFuncAttributeMaxDynamicSharedMemorySize, smemA2);

    split_w<<<768, 256>>>(W_lin, W_out, p_wlh, p_woh);

    // ---- blocks 1 & 2: proj, then fused attention+outproj+LN ----
    proj_mma<float><<<dim3(BS/64, 2, 2), 256, smemP>>>(
        q_emb, s_emb, p_wlh, 32768, b_lin, 256, p_qk0, p_qk1);
    fused_ao<<<dim3(BS/32, 2), 256, smemF>>>(
        p_qk0, p_qk1, p_woh, 65536,
        b_out, q_emb, s_emb, ln_g, ln_b, 256, p_hq, p_hs, qs);

    // ---- block 3 ----
    proj_mma<__half><<<dim3(BS/64, 2, 2), 256, smemP>>>(
        p_hq, p_hs, p_wlh + 65536, 0, b_lin + 512, 0, p_qk0, p_v);
    attn_two<<<dim3(Ssz/32, Bsz), 256, smemA2>>>(p_qk0, p_v, p_ath0);
    outln_b3<<<BS/64, 256, smemO>>>(
        p_ath0, p_woh + 131072, b_out + 512, p_hq,
        ln_g + 512, ln_b + 512, z);
}

// round 14
// speedup vs baseline: 1.0061x; 1.0061x over previous
#include <cuda_runtime.h>
#include <cuda_fp16.h>
#include <cstdint>

#define Bsz 32
#define Ssz 2048
#define BS (Bsz*Ssz)   // 65536 rows
#define WIN 44         // attention smem window rows (32 + 2*6 halo)

// ---------------- scratch (device globals; no allocation) ----------------
__device__ __half g_qk0[(size_t)BS*256];
__device__ __half g_qk1[(size_t)BS*256];
__device__ __half g_v  [(size_t)BS*256];
__device__ __half g_hq [(size_t)BS*256];
__device__ __half g_hs [(size_t)BS*256];
__device__ __half g_ath0[(size_t)BS*256];
__device__ __half g_wlh[3*2*128*128];
__device__ __half g_woh[3*256*256];

// ================= helpers =================
__device__ __forceinline__ uint32_t smem_u32(const void* p) {
    uint32_t a;
    asm("{ .reg .u64 t; cvta.to.shared.u64 t, %1; cvt.u32.u64 %0, t; }"
        : "=r"(a) : "l"(p));
    return a;
}
__device__ __forceinline__ void ldsm4(uint32_t r[4], uint32_t addr) {
    asm volatile("ldmatrix.sync.aligned.m8n8.x4.shared.b16 {%0,%1,%2,%3}, [%4];"
                 : "=r"(r[0]), "=r"(r[1]), "=r"(r[2]), "=r"(r[3]) : "r"(addr));
}
__device__ __forceinline__ void mma_f16(float4& c, const uint32_t a[4],
                                        uint32_t b0, uint32_t b1) {
    asm volatile(
        "mma.sync.aligned.m16n8k16.row.col.f32.f16.f16.f32 "
        "{%0,%1,%2,%3}, {%4,%5,%6,%7}, {%8,%9}, {%0,%1,%2,%3};"
        : "+f"(c.x), "+f"(c.y), "+f"(c.z), "+f"(c.w)
        : "r"(a[0]), "r"(a[1]), "r"(a[2]), "r"(a[3]), "r"(b0), "r"(b1));
}
__device__ __forceinline__ void cp16(uint32_t dst, const void* src) {
    asm volatile("cp.async.cg.shared.global [%0], [%1], 16;"
                 :: "r"(dst), "l"(src) : "memory");
}

// Fill a 64-row x 64-col chunk into fp16 smem (row stride 72 halves), 256 threads.
__device__ __forceinline__ void fill_hi64(const float* __restrict__ src, int stride,
                                          uint32_t* __restrict__ hi, int tid) {
    #pragma unroll
    for (int it = 0; it < 8; it++) {
        int idx = tid + it * 256;
        int row = idx >> 5, c2 = idx & 31;
        float2 v = *(const float2*)(src + (size_t)row * stride + c2 * 2);
        __half2 h = __floats2half2_rn(v.x, v.y);
        hi[row * 36 + c2] = *reinterpret_cast<uint32_t*>(&h);
    }
}
__device__ __forceinline__ void fill_hi64(const __half* __restrict__ src, int stride,
                                          uint32_t* __restrict__ hi, int tid) {
    #pragma unroll
    for (int it = 0; it < 8; it++) {
        int idx = tid + it * 256;
        int row = idx >> 5, c2 = idx & 31;
        hi[row * 36 + c2] = *(const uint32_t*)(src + (size_t)row * stride + c2 * 2);
    }
}
__device__ __forceinline__ float2 ld2f(const float* p) { return *(const float2*)p; }
__device__ __forceinline__ float2 ld2f(const __half* p) {
    uint32_t r = *(const uint32_t*)p;
    __half2 h = *reinterpret_cast<__half2*>(&r);
    return make_float2(__low2float(h), __high2float(h));
}
__device__ __forceinline__ void st2f(float* p, float2 v) { *(float2*)p = v; }
__device__ __forceinline__ void st2f(__half* p, float2 v) {
    __half2 h = __floats2half2_rn(v.x, v.y);
    *(uint32_t*)p = *reinterpret_cast<uint32_t*>(&h);
}

// ================= weight fp16 prep =================
__global__ void split_w(const float* __restrict__ Wl, const float* __restrict__ Wo,
                        __half* __restrict__ wlh, __half* __restrict__ woh)
{
    int i = blockIdx.x * 256 + threadIdx.x;
    if (i < 3*2*128*128) wlh[i] = __float2half_rn(Wl[i]);
    if (i < 3*256*256)   woh[i] = __float2half_rn(Wo[i]);
}

// ================= projection GEMM (64-row tile, 256 thr, 2 CTA/SM) =================
#define PR_BIAS 33792u
#define PR_SMEM 34304u

template<typename TIN>
__global__ __launch_bounds__(256) void proj_mma(
    const TIN* __restrict__ x0, const TIN* __restrict__ x1,
    const __half* __restrict__ whi, int wstep,
    const float* __restrict__ bias, int bstep,
    __half* __restrict__ out0, __half* __restrict__ out1)
{
    extern __shared__ __align__(16) char sm[];
    uint32_t* Ahi = (uint32_t*)(sm);
    char* Bhi = sm + 9216;
    float* sbias  = (float*)(sm + PR_BIAS);
    float* stg    = (float*)sm;

    const int chain = blockIdx.z;
    const TIN* x = chain ? x1 : x0;
    __half* out = chain ? out1 : out0;
    const int branch = blockIdx.y;
    const int r0 = blockIdx.x * 64;
    const int tid = threadIdx.x, lane = tid & 31, wid = tid >> 5;
    const int m0 = (wid >> 2) * 32, n0 = (wid & 3) * 32;

    const float* bp = bias + chain * bstep + branch * 128;
    if (tid < 128) sbias[tid] = bp[tid];

    const uint32_t sA = smem_u32(Ahi), sB = smem_u32(Bhi);
    const int a_row = lane & 15, a_kh = (lane >> 4) << 3;
    const int b_n = (lane & 7) + ((lane >> 4) << 3);
    const int b_kh = ((lane >> 3) & 1) << 3;

    float4 acc[2][4];
    #pragma unroll
    for (int i = 0; i < 2; i++)
        #pragma unroll
        for (int j = 0; j < 4; j++) acc[i][j] = make_float4(0.f, 0.f, 0.f, 0.f);

    const TIN* xp = x + (size_t)r0 * 256 + branch * 128;
    const __half* whb = whi + (size_t)chain * wstep + (size_t)branch * 128 * 128;

    uint32_t aAddr[2], bAddr[2];
    aAddr[0] = sA + ((m0 + a_row) * 72 + a_kh) * 2;
    aAddr[1] = sA + ((m0 + 16 + a_row) * 72 + a_kh) * 2;
    bAddr[0] = sB + ((n0 + b_n) * 72 + b_kh) * 2;
    bAddr[1] = sB + ((n0 + 16 + b_n) * 72 + b_kh) * 2;

    for (int kc = 0; kc < 128; kc += 64) {
        fill_hi64(xp + kc, 256, Ahi, tid);
        #pragma unroll
        for (int it = 0; it < 4; it++) {
            int idx = tid + it * 256;
            int row = idx >> 3, u = idx & 7;
            *(uint4*)(Bhi + row * 144 + u * 16) =
                *(const uint4*)(whb + row * 128 + kc + u * 8);
        }
        __syncthreads();
        #pragma unroll
        for (int ks = 0; ks < 4; ks++) {
            uint32_t ah[2][4], bh[2][4];
            #pragma unroll
            for (int mt = 0; mt < 2; mt++) ldsm4(ah[mt], aAddr[mt] + ks * 32);
            #pragma unroll
            for (int bt = 0; bt < 2; bt++) ldsm4(bh[bt], bAddr[bt] + ks * 32);
            #pragma unroll
            for (int mt = 0; mt < 2; mt++)
                #pragma unroll
                for (int bt = 0; bt < 2; bt++)
                    #pragma unroll
                    for (int sub = 0; sub < 2; sub++)
                        mma_f16(acc[mt][bt * 2 + sub], ah[mt],
                                bh[bt][sub*2], bh[bt][sub*2+1]);
        }
        __syncthreads();
    }

    #pragma unroll
    for (int mt = 0; mt < 2; mt++) {
        int rb = m0 + mt * 16 + (lane >> 2);
        #pragma unroll
        for (int nt = 0; nt < 4; nt++) {
            int j = n0 + nt * 8 + (lane & 3) * 2;
            int p0 = ((j & 31) << 2) + (j >> 5);
            int p1 = (((j + 1) & 31) << 2) + ((j + 1) >> 5);
            float4 a = acc[mt][nt];
            stg[rb * 132 + p0]       = a.x + sbias[j];
            stg[rb * 132 + p1]       = a.y + sbias[j + 1];
            stg[(rb + 8) * 132 + p0] = a.z + sbias[j];
            stg[(rb + 8) * 132 + p1] = a.w + sbias[j + 1];
        }
    }
    __syncthreads();
    #pragma unroll
    for (int it = 0; it < 8; it++) {
        int idx = tid + it * 256;
        int row = idx >> 5, q = idx & 31;
        float4 v = *(const float4*)(stg + row * 132 + q * 4);
        __half2 h0 = __floats2half2_rn(v.x, v.y);
        __half2 h1 = __floats2half2_rn(v.z, v.w);
        uint2 u = make_uint2(*reinterpret_cast<uint32_t*>(&h0),
                             *reinterpret_cast<uint32_t*>(&h1));
        *(uint2*)(out + (size_t)(r0 + row) * 256 + branch * 128 + q * 4) = u;
    }
}

// ================= FUSED attention + out-proj + residual + LN (blocks 1&2) =================
// 32 output rows/CTA + 12-row halo; QK==V. W double-buffered in K=32 chunks
// (stride 40 halves) so loads hide behind attention then pipeline behind MMA.
// Layout: A 18432 | W0 20480 | W1 20480 | qk 23936 | sum/sq 1024 = 84352 -> 2 CTA/SM.
#define FA_A    0u
#define FA_W0   18432u
#define FA_W1   38912u
#define FA_QK   59392u
#define FA_SUM  83328u
#define FA_SQ   83840u
#define FA_SMEM 84352u

__global__ __launch_bounds__(256) void fused_ao(
    const __half* __restrict__ qk0, const __half* __restrict__ qk1,
    const __half* __restrict__ Whi, int wstep,
    const float* __restrict__ bo, const float* __restrict__ xr0,
    const float* __restrict__ xr1,
    const float* __restrict__ g, const float* __restrict__ bb, int pstep,
    __half* __restrict__ out0, __half* __restrict__ out1,
    float* __restrict__ qs)
{
    extern __shared__ __align__(16) char sm[];
    const int chain = blockIdx.y;
    const __half* QK = chain ? qk1 : qk0;
    const __half* Wp = Whi + (size_t)chain * wstep;
    const float* xres = chain ? xr1 : xr0;
    const float* bop = bo + chain * pstep;
    const float* gp  = g  + chain * pstep;
    const float* bbp = bb + chain * pstep;
    __half* out = chain ? out1 : out0;

    const int r0 = blockIdx.x * 32;
    const int b = r0 >> 11, s0 = r0 & 2047;
    const int tid = threadIdx.x, lane = tid & 31, wid = tid >> 5;
    const int m0 = (wid >> 2) * 16, n0 = (wid & 3) * 64;
    const uint32_t sb = smem_u32(sm);
    uint32_t* sQK32 = (uint32_t*)(sm + FA_QK);
    uint16_t* Asm = (uint16_t*)(sm + FA_A);
    const uint32_t sA = sb + FA_A;

    // W chunk load: K=32 slice, 256 rows x 4 quads, row stride 80 B
    auto loadW = [&](int kc, uint32_t wb) {
        const __half* wsrc = Wp + kc * 32;
        #pragma unroll
        for (int it = 0; it < 4; it++) {
            int idx = tid + it * 256;
            int row = idx >> 2, u = idx & 3;
            cp16(wb + row * 80 + u * 16, wsrc + (size_t)row * 256 + u * 8);
        }
        asm volatile("cp.async.commit_group;" ::: "memory");
    };
    loadW(0, sb + FA_W0);   // hide both under attention phase
    loadW(1, sb + FA_W1);

    // L2 prefetch of the residual tile (consumed in epilogue)
    {
        const float* pf = xres + (size_t)(r0 + (tid >> 3)) * 256 + (tid & 7) * 32;
        asm volatile("prefetch.global.L2 [%0];" :: "l"(pf));
    }

    // qk window: 44 rows x 128 fp16-pairs, skewed (row stride 136 u32, head stride 17)
    for (int idx = tid; idx < 44 * 128; idx += 256) {
        int w = idx >> 7, p = idx & 127;
        int s = s0 + w - 6;
        uint32_t v = 0;
        if (s >= 0 && s < Ssz)
            v = ((const uint32_t*)QK)[((size_t)b * Ssz + s) * 128 + p];
        sQK32[w * 136 + (p >> 4) * 17 + (p & 15)] = v;
    }
    __syncthreads();

    // ---- attention: 1 task per thread (32 rows x 8 heads) ----
    {
        const int sl = tid >> 3, h = tid & 7;
        const int dil = (h < 4) ? 3 : 1;
        const float scale = 0.1767766952966369f;
        const uint32_t* qp = sQK32 + (sl + 6) * 136 + h * 17;

        float qv[32];
        #pragma unroll
        for (int j = 0; j < 16; j++) {
            __half2 hh = *(const __half2*)(qp + j);
            qv[2*j] = __low2float(hh); qv[2*j+1] = __high2float(hh);
        }
        float sc[5];
        #pragma unroll
        for (int k = 0; k < 5; k++) {
            const uint32_t* kp = sQK32 + (sl + 6 + (k - 2) * dil) * 136 + h * 17;
            float d = 0.f;
            #pragma unroll
            for (int j = 0; j < 16; j++) {
                __half2 kh = *(const __half2*)(kp + j);
                d += qv[2*j] * __low2float(kh) + qv[2*j+1] * __high2float(kh);
            }
            sc[k] = d * scale;
        }
        float mx = sc[0];
        #pragma unroll
        for (int k = 1; k < 5; k++) mx = fmaxf(mx, sc[k]);
        float ex[5], sum = 0.f;
        #pragma unroll
        for (int k = 0; k < 5; k++) { ex[k] = __expf(sc[k] - mx); sum += ex[k]; }
        float inv = 1.f / sum;
        #pragma unroll
        for (int k = 0; k < 5; k++) ex[k] *= inv;

        // output -> A smem (ldmatrix layout; chunk = h>>1, half = h&1)
        const uint32_t* v0 = sQK32 + (sl + 6 - 2 * dil) * 136 + h * 17;
        const int vstep = dil * 136;
        int aoff = (h >> 1) * 2304 + sl * 72 + (h & 1) * 32;  // halves
        #pragma unroll
        for (int j = 0; j < 16; j++) {
            float ox = 0.f, oy = 0.f;
            #pragma unroll
            for (int k = 0; k < 5; k++) {
                __half2 vh = *(const __half2*)(v0 + k * vstep + j);
                ox += ex[k] * __low2float(vh);
                oy += ex[k] * __high2float(vh);
            }
            __half2 oh = __floats2half2_rn(ox, oy);
            *(uint32_t*)(Asm + aoff + 2 * j) = *reinterpret_cast<uint32_t*>(&oh);
        }

        if (chain) {
            float* sp = qs + (((size_t)b * 8 + h) * Ssz + s0 + sl) * 5;
            #pragma unroll
            for (int k = 0; k < 5; k++) sp[k] = ex[k];
        }
    }
    __syncthreads();   // A writes visible; W0/W1 still possibly in flight

    // ---- GEMM: 32x256, K=256 in 8 K32-chunks, W double-buffered ----
    const int a_row = lane & 15, a_kh = (lane >> 4) << 3;
    const int b_n = (lane & 7) + ((lane >> 4) << 3);
    const int b_kh = ((lane >> 3) & 1) << 3;
    const uint32_t aOffBase = ((m0 + a_row) * 72 + a_kh) * 2;
    const uint32_t bOff = (n0 + b_n) * 80 + b_kh * 2;

    float4 acc[8];
    #pragma unroll
    for (int j = 0; j < 8; j++) acc[j] = make_float4(0.f, 0.f, 0.f, 0.f);

    #pragma unroll 1
    for (int kc = 0; kc < 8; kc++) {
        if (kc < 7) asm volatile("cp.async.wait_group 1;" ::: "memory");
        else        asm volatile("cp.async.wait_group 0;" ::: "memory");
        __syncthreads();
        uint32_t wb = sb + ((kc & 1) ? FA_W1 : FA_W0);
        uint32_t bAddr = wb + bOff;
        uint32_t aB = sA + (kc >> 1) * 4608 + (kc & 1) * 64 + aOffBase;
        #pragma unroll
        for (int ks = 0; ks < 2; ks++) {
            uint32_t ah[4];
            ldsm4(ah, aB + ks * 32);
            #pragma unroll
            for (int nb = 0; nb < 4; nb++) {
                uint32_t bh[4];
                ldsm4(bh, bAddr + nb * 1280 + ks * 32);
                mma_f16(acc[nb * 2],     ah, bh[0], bh[1]);
                mma_f16(acc[nb * 2 + 1], ah, bh[2], bh[3]);
            }
        }
        __syncthreads();
        if (kc + 2 < 8) loadW(kc + 2, wb);
    }

    // ---- epilogue: bias + residual + LN ----
    float sums[2] = {0.f, 0.f}, sqs2[2] = {0.f, 0.f};
    const int rl = r0 + m0 + (lane >> 2);
    #pragma unroll
    for (int nt = 0; nt < 8; nt++) {
        int c = n0 + nt * 8 + (lane & 3) * 2;
        float2 bo2 = *(const float2*)(bop + c);
        float2 xl = *(const float2*)(xres + (size_t)rl * 256 + c);
        float2 xh = *(const float2*)(xres + (size_t)(rl + 8) * 256 + c);
        float4& a = acc[nt];
        a.x += bo2.x + xl.x; a.y += bo2.y + xl.y;
        a.z += bo2.x + xh.x; a.w += bo2.y + xh.y;
        sums[0] += a.x + a.y; sqs2[0] += a.x*a.x + a.y*a.y;
        sums[1] += a.z + a.w; sqs2[1] += a.z*a.z + a.w*a.w;
    }
    #pragma unroll
    for (int hf = 0; hf < 2; hf++) {
        sums[hf] += __shfl_xor_sync(0xffffffffu, sums[hf], 1);
        sums[hf] += __shfl_xor_sync(0xffffffffu, sums[hf], 2);
        sqs2[hf] += __shfl_xor_sync(0xffffffffu, sqs2[hf], 1);
        sqs2[hf] += __shfl_xor_sync(0xffffffffu, sqs2[hf], 2);
    }
    float* ssum = (float*)(sm + FA_SUM);
    float* ssq  = (float*)(sm + FA_SQ);
    if ((lane & 3) == 0) {
        #pragma unroll
        for (int hf = 0; hf < 2; hf++) {
            int row = m0 + hf * 8 + (lane >> 2);
            ssum[(wid & 3) * 32 + row] = sums[hf];
            ssq [(wid & 3) * 32 + row] = sqs2[hf];
        }
    }
    __syncthreads();
    float mu[2], rs[2];
    #pragma unroll
    for (int hf = 0; hf < 2; hf++) {
        int row = m0 + hf * 8 + (lane >> 2);
        float s = ssum[row] + ssum[32 + row] + ssum[64 + row] + ssum[96 + row];
        float q = ssq[row] + ssq[32 + row] + ssq[64 + row] + ssq[96 + row];
        float m = s * (1.f / 256.f);
        mu[hf] = m;
        rs[hf] = rsqrtf(q * (1.f / 256.f) - m * m + 1e-5f);
    }
    #pragma unroll
    for (int nt = 0; nt < 8; nt++) {
        int c = n0 + nt * 8 + (lane & 3) * 2;
        float2 g2 = *(const float2*)(gp + c);
        float2 b2 = *(const float2*)(bbp + c);
        float4 a = acc[nt];
        float2 o1, o2;
        o1.x = (a.x - mu[0]) * rs[0] * g2.x + b2.x;
        o1.y = (a.y - mu[0]) * rs[0] * g2.y + b2.y;
        o2.x = (a.z - mu[1]) * rs[1] * g2.x + b2.x;
        o2.y = (a.w - mu[1]) * rs[1] * g2.y + b2.y;
        st2f(out + (size_t)rl * 256 + c, o1);
        st2f(out + (size_t)(rl + 8) * 256 + c, o2);
    }
}

// ================= out-proj + residual + LN for block 3 =================
#define OLS_STAGE 46080u
#define OLS_SUM   92160u
#define OLS_SQ    93184u
#define OLS_SMEM  94208u

__global__ __launch_bounds__(256) void outln_b3(
    const __half* __restrict__ Ahi,
    const __half* __restrict__ Wp,
    const float* __restrict__ bop, const __half* __restrict__ xres,
    const float* __restrict__ gp, const float* __restrict__ bbp,
    float* __restrict__ out)
{
    extern __shared__ __align__(16) char sm[];
    const int r0 = blockIdx.x * 64;
    const int tid = threadIdx.x, lane = tid & 31, wid = tid >> 5;
    const int m0 = (wid >> 2) * 32, n0 = (wid & 3) * 64;
    const uint32_t sb = smem_u32(sm);

    auto load_chunk = [&](int kc) {
        uint32_t st = sb + (uint32_t)(kc & 1) * OLS_STAGE;
        const __half* ah = Ahi + (size_t)r0 * 256 + kc * 64;
        const __half* wh = Wp + kc * 64;
        #pragma unroll
        for (int it = 0; it < 2; it++) {
            int idx = tid + it * 256;
            int row = idx >> 3, u = idx & 7;
            cp16(st + row * 144 + u * 16, ah + (size_t)row * 256 + u * 8);
        }
        #pragma unroll
        for (int it = 0; it < 8; it++) {
            int idx = tid + it * 256;
            int row = idx >> 3, u = idx & 7;
            cp16(st + 9216u + row * 144 + u * 16, wh + (size_t)row * 256 + u * 8);
        }
        asm volatile("cp.async.commit_group;" ::: "memory");
    };

    const int a_row = lane & 15, a_kh = (lane >> 4) << 3;
    const int b_n = (lane & 7) + ((lane >> 4) << 3);
    const int b_kh = ((lane >> 3) & 1) << 3;
    const uint32_t aOff = ((m0 + a_row) * 72 + a_kh) * 2;
    const uint32_t bOff = 9216u + ((n0 + b_n) * 72 + b_kh) * 2;

    float4 acc[2][8];
    #pragma unroll
    for (int i = 0; i < 2; i++)
        #pragma unroll
        for (int j = 0; j < 8; j++) acc[i][j] = make_float4(0.f, 0.f, 0.f, 0.f);

    load_chunk(0);
    #pragma unroll 1
    for (int kc = 0; kc < 4; kc++) {
        if (kc < 3) {
            load_chunk(kc + 1);
            asm volatile("cp.async.wait_group 1;" ::: "memory");
        } else {
            asm volatile("cp.async.wait_group 0;" ::: "memory");
        }
        __syncthreads();
        uint32_t st = sb + (uint32_t)(kc & 1) * OLS_STAGE;
        uint32_t aB = st + aOff, bB = st + bOff;
        #pragma unroll
        for (int ks = 0; ks < 4; ks++) {
            uint32_t ah[2][4];
            ldsm4(ah[0], aB + ks * 32);
            ldsm4(ah[1], aB + 2304 + ks * 32);
            #pragma unroll
            for (int nb = 0; nb < 4; nb++) {
                uint32_t bh[4];
                ldsm4(bh, bB + nb * 2304 + ks * 32);
                #pragma unroll
                for (int mt = 0; mt < 2; mt++)
                    #pragma unroll
                    for (int sub = 0; sub < 2; sub++)
                        mma_f16(acc[mt][nb * 2 + sub], ah[mt],
                                bh[sub*2], bh[sub*2+1]);
            }
        }
        __syncthreads();
    }

    float sums[2][2] = {{0.f,0.f},{0.f,0.f}}, sqs[2][2] = {{0.f,0.f},{0.f,0.f}};
    #pragma unroll
    for (int mt = 0; mt < 2; mt++) {
        int rl = r0 + m0 + mt * 16 + (lane >> 2);
        #pragma unroll
        for (int nt = 0; nt < 8; nt++) {
            int c = n0 + nt * 8 + (lane & 3) * 2;
            float2 bo2 = *(const float2*)(bop + c);
            float2 xl = ld2f(xres + (size_t)rl * 256 + c);
            float2 xh = ld2f(xres + (size_t)(rl + 8) * 256 + c);
            float4& a = acc[mt][nt];
            a.x += bo2.x + xl.x; a.y += bo2.y + xl.y;
            a.z += bo2.x + xh.x; a.w += bo2.y + xh.y;
            sums[mt][0] += a.x + a.y; sqs[mt][0] += a.x*a.x + a.y*a.y;
            sums[mt][1] += a.z + a.w; sqs[mt][1] += a.z*a.z + a.w*a.w;
        }
    }
    #pragma unroll
    for (int mt = 0; mt < 2; mt++)
        #pragma unroll
        for (int hf = 0; hf < 2; hf++) {
            sums[mt][hf] += __shfl_xor_sync(0xffffffffu, sums[mt][hf], 1);
            sums[mt][hf] += __shfl_xor_sync(0xffffffffu, sums[mt][hf], 2);
            sqs[mt][hf]  += __shfl_xor_sync(0xffffffffu, sqs[mt][hf], 1);
            sqs[mt][hf]  += __shfl_xor_sync(0xffffffffu, sqs[mt][hf], 2);
        }
    float* ssum = (float*)(sm + OLS_SUM);
    float* ssq  = (float*)(sm + OLS_SQ);
    if ((lane & 3) == 0) {
        #pragma unroll
        for (int mt = 0; mt < 2; mt++)
            #pragma unroll
            for (int hf = 0; hf < 2; hf++) {
                int row = m0 + mt * 16 + hf * 8 + (lane >> 2);
                ssum[(wid & 3) * 64 + row] = sums[mt][hf];
                ssq [(wid & 3) * 64 + row] = sqs[mt][hf];
            }
    }
    __syncthreads();
    float mu[2][2], rs[2][2];
    #pragma unroll
    for (int mt = 0; mt < 2; mt++)
        #pragma unroll
        for (int hf = 0; hf < 2; hf++) {
            int row = m0 + mt * 16 + hf * 8 + (lane >> 2);
            float s = ssum[row] + ssum[64 + row] + ssum[128 + row] + ssum[192 + row];
            float q = ssq[row] + ssq[64 + row] + ssq[128 + row] + ssq[192 + row];
            float m = s * (1.f / 256.f);
            mu[mt][hf] = m;
            rs[mt][hf] = rsqrtf(q * (1.f / 256.f) - m * m + 1e-5f);
        }
    #pragma unroll
    for (int mt = 0; mt < 2; mt++) {
        int rl = r0 + m0 + mt * 16 + (lane >> 2);
        #pragma unroll
        for (int nt = 0; nt < 8; nt++) {
            int c = n0 + nt * 8 + (lane & 3) * 2;
            float2 g2 = *(const float2*)(gp + c);
            float2 b2 = *(const float2*)(bbp + c);
            float4 a = acc[mt][nt];
            float2 o1, o2;
            o1.x = (a.x - mu[mt][0]) * rs[mt][0] * g2.x + b2.x;
            o1.y = (a.y - mu[mt][0]) * rs[mt][0] * g2.y + b2.y;
            o2.x = (a.z - mu[mt][1]) * rs[mt][1] * g2.x + b2.x;
            o2.y = (a.w - mu[mt][1]) * rs[mt][1] * g2.y + b2.y;
            st2f(out + (size_t)rl * 256 + c, o1);
            st2f(out + (size_t)(rl + 8) * 256 + c, o2);
        }
    }
}

// ================= attention for block 3 (QK != V), fp32 smem path =================
#define ATT_STRIDE 288
#define ATT2_SMEM (2 * WIN * ATT_STRIDE * 4)   // 101376

__device__ __forceinline__ float4 h4_to_f4(uint2 raw) {
    __half2 h0 = *reinterpret_cast<__half2*>(&raw.x);
    __half2 h1 = *reinterpret_cast<__half2*>(&raw.y);
    return make_float4(__low2float(h0), __high2float(h0),
                       __low2float(h1), __high2float(h1));
}

__global__ __launch_bounds__(256) void attn_two(
    const __half* __restrict__ QK, const __half* __restrict__ V,
    __half* __restrict__ ath)
{
    extern __shared__ float smf[];
    float* sQK = smf;
    float* sV  = smf + WIN * ATT_STRIDE;
    const int b  = blockIdx.y;
    const int s0 = blockIdx.x * 32;
    const int tid = threadIdx.x;

    for (int idx = tid; idx < WIN * 64; idx += 256) {
        int w = idx >> 6, c4 = idx & 63;
        int s = s0 + w - 6;
        float4 vq = make_float4(0.f, 0.f, 0.f, 0.f);
        float4 vv = vq;
        if (s >= 0 && s < Ssz) {
            size_t off = ((size_t)b * Ssz + s) * 64 + c4;
            vq = h4_to_f4(((const uint2*)QK)[off]);
            vv = h4_to_f4(((const uint2*)V)[off]);
        }
        int sc = w * ATT_STRIDE + (c4 >> 3) * 36 + (c4 & 7) * 4;
        *(float4*)(sQK + sc) = vq;
        *(float4*)(sV + sc)  = vv;
    }
    __syncthreads();

    const int sl = tid >> 3, h = tid & 7;
    const int dil = (h < 4) ? 3 : 1;
    const float scale = 0.1767766952966369f;
    const int colb = h * 36;

    float4 q[8];
    {
        const float* qr = sQK + (sl + 6) * ATT_STRIDE + colb;
        #pragma unroll
        for (int j = 0; j < 8; j++) q[j] = *(const float4*)(qr + j * 4);
    }
    float sc[5];
    #pragma unroll
    for (int k = 0; k < 5; k++) {
        const float* kr = sQK + (sl + 6 + (k - 2) * dil) * ATT_STRIDE + colb;
        float d = 0.f;
        #pragma unroll
        for (int j = 0; j < 8; j++) {
            float4 kv = *(const float4*)(kr + j * 4);
            d += q[j].x * kv.x + q[j].y * kv.y + q[j].z * kv.z + q[j].w * kv.w;
        }
        sc[k] = d * scale;
    }
    float mx = sc[0];
    #pragma unroll
    for (int k = 1; k < 5; k++) mx = fmaxf(mx, sc[k]);
    float ex[5], sum = 0.f;
    #pragma unroll
    for (int k = 0; k < 5; k++) { ex[k] = __expf(sc[k] - mx); sum += ex[k]; }
    float inv = 1.f / sum;
    #pragma unroll
    for (int k = 0; k < 5; k++) ex[k] *= inv;

    size_t base = ((size_t)b * Ssz + s0 + sl) * 256 + h * 32;
    const float* v0 = sV + (sl + 6 - 2 * dil) * ATT_STRIDE + colb;
    const int vstep = dil * ATT_STRIDE;
    uint32_t Hw[16];
    #pragma unroll
    for (int j = 0; j < 8; j++) {
        float4 o = make_float4(0.f, 0.f, 0.f, 0.f);
        #pragma unroll
        for (int k = 0; k < 5; k++) {
            float4 vv = *(const float4*)(v0 + k * vstep + j * 4);
            o.x += ex[k] * vv.x; o.y += ex[k] * vv.y;
            o.z += ex[k] * vv.z; o.w += ex[k] * vv.w;
        }
        __half2 h0 = __floats2half2_rn(o.x, o.y);
        __half2 h1 = __floats2half2_rn(o.z, o.w);
        Hw[2*j]   = *reinterpret_cast<uint32_t*>(&h0);
        Hw[2*j+1] = *reinterpret_cast<uint32_t*>(&h1);
    }
    #pragma unroll
    for (int u = 0; u < 4; u++) {
        uint4 vh = make_uint4(Hw[u*4], Hw[u*4+1], Hw[u*4+2], Hw[u*4+3]);
        *(uint4*)((char*)(ath + base) + u * 16) = vh;
    }
}

// ================= launch =================
extern "C" void kernel_launch(void* const* d_in, const int* in_sizes, int n_in,
                              void* d_out, int out_size)
{
    (void)in_sizes; (void)n_in; (void)out_size;
    const float* q_emb = (const float*)d_in[0];
    const float* s_emb = (const float*)d_in[1];
    const float* W_lin = (const float*)d_in[3];
    const float* b_lin = (const float*)d_in[4];
    const float* W_out = (const float*)d_in[5];
    const float* b_out = (const float*)d_in[6];
    const float* ln_g  = (const float*)d_in[7];
    const float* ln_b  = (const float*)d_in[8];

    float* outp = (float*)d_out;
    float* z  = outp;
    float* qs = outp + (size_t)BS * 256;

    __half *p_qk0, *p_qk1, *p_v, *p_hq, *p_hs, *p_ath0, *p_wlh, *p_woh;
    cudaGetSymbolAddress((void**)&p_qk0, g_qk0);
    cudaGetSymbolAddress((void**)&p_qk1, g_qk1);
    cudaGetSymbolAddress((void**)&p_v,   g_v);
    cudaGetSymbolAddress((void**)&p_hq,  g_hq);
    cudaGetSymbolAddress((void**)&p_hs,  g_hs);
    cudaGetSymbolAddress((void**)&p_ath0, g_ath0);
    cudaGetSymbolAddress((void**)&p_wlh, g_wlh);
    cudaGetSymbolAddress((void**)&p_woh, g_woh);

    const int smemP  = (int)PR_SMEM;
    const int smemF  = (int)FA_SMEM;    // 84352
    const int smemO  = (int)OLS_SMEM;
    const int smemA2 = ATT2_SMEM;
    cudaFuncSetAttribute(proj_mma<float>,  cudaFuncAttributeMaxDynamicSharedMemorySize, smemP);
    cudaFuncSetAttribute(proj_mma<__half>, cudaFuncAttributeMaxDynamicSharedMemorySize, smemP);
    cudaFuncSetAttribute(fused_ao, cudaFuncAttributeMaxDynamicSharedMemorySize, smemF);
    cudaFuncSetAttribute(outln_b3, cudaFuncAttributeMaxDynamicSharedMemorySize, smemO);
    cudaFuncSetAttribute(attn_two, cudaFuncAttributeMaxDynamicSharedMemorySize, smemA2);

    split_w<<<768, 256>>>(W_lin, W_out, p_wlh, p_woh);

    // ---- blocks 1 & 2: proj, then fused attention+outproj+LN ----
    proj_mma<float><<<dim3(BS/64, 2, 2), 256, smemP>>>(
        q_emb, s_emb, p_wlh, 32768, b_lin, 256, p_qk0, p_qk1);
    fused_ao<<<dim3(BS/32, 2), 256, smemF>>>(
        p_qk0, p_qk1, p_woh, 65536,
        b_out, q_emb, s_emb, ln_g, ln_b, 256, p_hq, p_hs, qs);

    // ---- block 3 ----
    proj_mma<__half><<<dim3(BS/64, 2, 2), 256, smemP>>>(
        p_hq, p_hs, p_wlh + 65536, 0, b_lin + 512, 0, p_qk0, p_v);
    attn_two<<<dim3(Ssz/32, Bsz), 256, smemA2>>>(p_qk0, p_v, p_ath0);
    outln_b3<<<BS/64, 256, smemO>>>(
        p_ath0, p_woh + 131072, b_out + 512, p_hq,
        ln_g + 512, ln_b + 512, z);
}

// round 16
// speedup vs baseline: 1.1771x; 1.1699x over previous
#include <cuda_runtime.h>
#include <cuda_fp16.h>
#include <cstdint>

#define Bsz 32
#define Ssz 2048
#define BS (Bsz*Ssz)   // 65536 rows
#define WIN 44         // attention smem window rows (32 + 2*6 halo)

// ---------------- scratch (device globals; no allocation) ----------------
__device__ __half g_qk0[(size_t)BS*256];
__device__ __half g_qk1[(size_t)BS*256];
__device__ __half g_v  [(size_t)BS*256];
__device__ __half g_hq [(size_t)BS*256];
__device__ __half g_hs [(size_t)BS*256];
__device__ __half g_ath0[(size_t)BS*256];
__device__ __half g_ath1[(size_t)BS*256];
__device__ __half g_wlh[3*2*128*128];
__device__ __half g_woh[3*256*256];

// ================= helpers =================
__device__ __forceinline__ uint32_t smem_u32(const void* p) {
    uint32_t a;
    asm("{ .reg .u64 t; cvta.to.shared.u64 t, %1; cvt.u32.u64 %0, t; }"
        : "=r"(a) : "l"(p));
    return a;
}
__device__ __forceinline__ void ldsm4(uint32_t r[4], uint32_t addr) {
    asm volatile("ldmatrix.sync.aligned.m8n8.x4.shared.b16 {%0,%1,%2,%3}, [%4];"
                 : "=r"(r[0]), "=r"(r[1]), "=r"(r[2]), "=r"(r[3]) : "r"(addr));
}
__device__ __forceinline__ void mma_f16(float4& c, const uint32_t a[4],
                                        uint32_t b0, uint32_t b1) {
    asm volatile(
        "mma.sync.aligned.m16n8k16.row.col.f32.f16.f16.f32 "
        "{%0,%1,%2,%3}, {%4,%5,%6,%7}, {%8,%9}, {%0,%1,%2,%3};"
        : "+f"(c.x), "+f"(c.y), "+f"(c.z), "+f"(c.w)
        : "r"(a[0]), "r"(a[1]), "r"(a[2]), "r"(a[3]), "r"(b0), "r"(b1));
}
__device__ __forceinline__ void cp16(uint32_t dst, const void* src) {
    asm volatile("cp.async.cg.shared.global [%0], [%1], 16;"
                 :: "r"(dst), "l"(src) : "memory");
}
__device__ __forceinline__ float2 ld2f(const float* p) { return *(const float2*)p; }
__device__ __forceinline__ float2 ld2f(const __half* p) {
    uint32_t r = *(const uint32_t*)p;
    __half2 h = *reinterpret_cast<__half2*>(&r);
    return make_float2(__low2float(h), __high2float(h));
}
__device__ __forceinline__ void st2f(float* p, float2 v) { *(float2*)p = v; }
__device__ __forceinline__ void st2f(__half* p, float2 v) {
    __half2 h = __floats2half2_rn(v.x, v.y);
    *(uint32_t*)p = *reinterpret_cast<uint32_t*>(&h);
}

// ================= weight fp16 prep =================
__global__ void split_w(const float* __restrict__ Wl, const float* __restrict__ Wo,
                        __half* __restrict__ wlh, __half* __restrict__ woh)
{
    int i = blockIdx.x * 256 + threadIdx.x;
    if (i < 3*2*128*128) wlh[i] = __float2half_rn(Wl[i]);
    if (i < 3*256*256)   woh[i] = __float2half_rn(Wo[i]);
}

// ================= projection GEMM v2 =================
// 64-row tile, K=128 single pass. W streamed via cp.async, hidden under the
// A fill/convert. Row stride 136 halves. smem: A 17408 | W 34816 | bias 512.
#define PR_A    0u
#define PR_W    17408u
#define PR_BIAS 52224u
#define PR_SMEM 52736u

// A fill: fp32 source (convert) or fp16 source (copy). Row stride 68 u32.
__device__ __forceinline__ void fillA(const float* __restrict__ src,
                                      uint32_t* __restrict__ A, int tid) {
    #pragma unroll
    for (int it = 0; it < 16; it++) {
        int idx = tid + it * 256;
        int row = idx >> 6, c2 = idx & 63;
        float2 v = *(const float2*)(src + (size_t)row * 256 + c2 * 2);
        __half2 h = __floats2half2_rn(v.x, v.y);
        A[row * 68 + c2] = *reinterpret_cast<uint32_t*>(&h);
    }
}
__device__ __forceinline__ void fillA(const __half* __restrict__ src,
                                      uint32_t* __restrict__ A, int tid) {
    const uint32_t* s32 = (const uint32_t*)src;
    #pragma unroll
    for (int it = 0; it < 16; it++) {
        int idx = tid + it * 256;
        int row = idx >> 6, c2 = idx & 63;
        A[row * 68 + c2] = s32[(size_t)row * 128 + c2];
    }
}

template<typename TIN>
__global__ __launch_bounds__(256) void proj_mma(
    const TIN* __restrict__ x0, const TIN* __restrict__ x1,
    const __half* __restrict__ whi, int wstep,
    const float* __restrict__ bias, int bstep,
    __half* __restrict__ out0, __half* __restrict__ out1)
{
    extern __shared__ __align__(16) char sm[];
    uint32_t* Ahi = (uint32_t*)(sm + PR_A);
    float* sbias  = (float*)(sm + PR_BIAS);
    float* stg    = (float*)sm;            // 64x132 fp32 = 33792 B, overlaps post-GEMM

    const int chain = blockIdx.z;
    const TIN* x = chain ? x1 : x0;
    __half* out = chain ? out1 : out0;
    const int branch = blockIdx.y;
    const int r0 = blockIdx.x * 64;
    const int tid = threadIdx.x, lane = tid & 31, wid = tid >> 5;
    const int m0 = (wid >> 2) * 32, n0 = (wid & 3) * 32;
    const uint32_t sb = smem_u32(sm);
    const uint32_t sA = sb + PR_A, sW = sb + PR_W;

    // 1) stream full W tile (128 rows x 256 B = 32 KB = 2048 cp16 ops)
    {
        const __half* wsrc = whi + (size_t)chain * wstep + (size_t)branch * 128 * 128;
        #pragma unroll
        for (int it = 0; it < 8; it++) {
            int idx = tid + it * 256;
            int row = idx >> 4, u = idx & 15;
            cp16(sW + row * 272 + u * 16, wsrc + (size_t)row * 128 + u * 8);
        }
        asm volatile("cp.async.commit_group;" ::: "memory");
    }
    if (tid < 128) sbias[tid] = bias[chain * bstep + branch * 128 + tid];

    // 2) A fill (conversion work hides W stream)
    fillA(x + (size_t)r0 * 256 + branch * 128, Ahi, tid);

    asm volatile("cp.async.wait_group 0;" ::: "memory");
    __syncthreads();

    // 3) single uninterrupted MMA loop over K=128 (8 K16 steps)
    const int a_row = lane & 15, a_kh = (lane >> 4) << 3;
    const int b_n = (lane & 7) + ((lane >> 4) << 3);
    const int b_kh = ((lane >> 3) & 1) << 3;
    uint32_t aAddr[2], bAddr[2];
    aAddr[0] = sA + ((m0 + a_row) * 136 + a_kh) * 2;
    aAddr[1] = sA + ((m0 + 16 + a_row) * 136 + a_kh) * 2;
    bAddr[0] = sW + ((n0 + b_n) * 136 + b_kh) * 2;
    bAddr[1] = sW + ((n0 + 16 + b_n) * 136 + b_kh) * 2;

    float4 acc[2][4];
    #pragma unroll
    for (int i = 0; i < 2; i++)
        #pragma unroll
        for (int j = 0; j < 4; j++) acc[i][j] = make_float4(0.f, 0.f, 0.f, 0.f);

    #pragma unroll
    for (int ks = 0; ks < 8; ks++) {
        uint32_t ah[2][4], bh[2][4];
        #pragma unroll
        for (int mt = 0; mt < 2; mt++) ldsm4(ah[mt], aAddr[mt] + ks * 32);
        #pragma unroll
        for (int bt = 0; bt < 2; bt++) ldsm4(bh[bt], bAddr[bt] + ks * 32);
        #pragma unroll
        for (int mt = 0; mt < 2; mt++)
            #pragma unroll
            for (int bt = 0; bt < 2; bt++)
                #pragma unroll
                for (int sub = 0; sub < 2; sub++)
                    mma_f16(acc[mt][bt * 2 + sub], ah[mt],
                            bh[bt][sub*2], bh[bt][sub*2+1]);
    }
    __syncthreads();

    // 4) epilogue: bias + permuted store to staging, then coalesced fp16 write
    #pragma unroll
    for (int mt = 0; mt < 2; mt++) {
        int rb = m0 + mt * 16 + (lane >> 2);
        #pragma unroll
        for (int nt = 0; nt < 4; nt++) {
            int j = n0 + nt * 8 + (lane & 3) * 2;
            int p0 = ((j & 31) << 2) + (j >> 5);
            int p1 = (((j + 1) & 31) << 2) + ((j + 1) >> 5);
            float4 a = acc[mt][nt];
            stg[rb * 132 + p0]       = a.x + sbias[j];
            stg[rb * 132 + p1]       = a.y + sbias[j + 1];
            stg[(rb + 8) * 132 + p0] = a.z + sbias[j];
            stg[(rb + 8) * 132 + p1] = a.w + sbias[j + 1];
        }
    }
    __syncthreads();
    #pragma unroll
    for (int it = 0; it < 8; it++) {
        int idx = tid + it * 256;
        int row = idx >> 5, q = idx & 31;
        float4 v = *(const float4*)(stg + row * 132 + q * 4);
        __half2 h0 = __floats2half2_rn(v.x, v.y);
        __half2 h1 = __floats2half2_rn(v.z, v.w);
        uint2 u = make_uint2(*reinterpret_cast<uint32_t*>(&h0),
                             *reinterpret_cast<uint32_t*>(&h1));
        *(uint2*)(out + (size_t)(r0 + row) * 256 + branch * 128 + q * 4) = u;
    }
}

// ================= out-proj + bias + residual + LN (R11 proven path) =================
#define OLS_STAGE 46080u
#define OLS_SUM   92160u
#define OLS_SQ    93184u
#define OLS_SMEM  94208u

template<typename TX, typename TO>
__global__ __launch_bounds__(256) void outln_mma(
    const __half* __restrict__ A0h, const __half* __restrict__ A1h,
    const __half* __restrict__ Whi, int wstep,
    const float* __restrict__ bo, const TX* __restrict__ xr0,
    const TX* __restrict__ xr1,
    const float* __restrict__ g, const float* __restrict__ bb, int pstep,
    TO* __restrict__ out0, TO* __restrict__ out1)
{
    extern __shared__ __align__(16) char sm[];
    const int chain = blockIdx.y;
    const __half* Ahi = chain ? A1h : A0h;
    const __half* Wp  = Whi + (size_t)chain * wstep;
    const TX* xres = chain ? xr1 : xr0;
    const float* bop = bo + chain * pstep;
    const float* gp  = g  + chain * pstep;
    const float* bbp = bb + chain * pstep;
    TO* out = chain ? out1 : out0;

    const int r0 = blockIdx.x * 64;
    const int tid = threadIdx.x, lane = tid & 31, wid = tid >> 5;
    const int m0 = (wid >> 2) * 32, n0 = (wid & 3) * 64;
    const uint32_t sb = smem_u32(sm);

    auto load_chunk = [&](int kc) {
        uint32_t st = sb + (uint32_t)(kc & 1) * OLS_STAGE;
        const __half* ah = Ahi + (size_t)r0 * 256 + kc * 64;
        const __half* wh = Wp + kc * 64;
        #pragma unroll
        for (int it = 0; it < 2; it++) {
            int idx = tid + it * 256;
            int row = idx >> 3, u = idx & 7;
            cp16(st + row * 144 + u * 16, ah + (size_t)row * 256 + u * 8);
        }
        #pragma unroll
        for (int it = 0; it < 8; it++) {
            int idx = tid + it * 256;
            int row = idx >> 3, u = idx & 7;
            cp16(st + 9216u + row * 144 + u * 16, wh + (size_t)row * 256 + u * 8);
        }
        asm volatile("cp.async.commit_group;" ::: "memory");
    };

    const int a_row = lane & 15, a_kh = (lane >> 4) << 3;
    const int b_n = (lane & 7) + ((lane >> 4) << 3);
    const int b_kh = ((lane >> 3) & 1) << 3;
    const uint32_t aOff = ((m0 + a_row) * 72 + a_kh) * 2;
    const uint32_t bOff = 9216u + ((n0 + b_n) * 72 + b_kh) * 2;

    float4 acc[2][8];
    #pragma unroll
    for (int i = 0; i < 2; i++)
        #pragma unroll
        for (int j = 0; j < 8; j++) acc[i][j] = make_float4(0.f, 0.f, 0.f, 0.f);

    load_chunk(0);
    #pragma unroll 1
    for (int kc = 0; kc < 4; kc++) {
        if (kc < 3) {
            load_chunk(kc + 1);
            asm volatile("cp.async.wait_group 1;" ::: "memory");
        } else {
            asm volatile("cp.async.wait_group 0;" ::: "memory");
        }
        __syncthreads();
        uint32_t st = sb + (uint32_t)(kc & 1) * OLS_STAGE;
        uint32_t aB = st + aOff, bB = st + bOff;
        #pragma unroll
        for (int ks = 0; ks < 4; ks++) {
            uint32_t ah[2][4];
            ldsm4(ah[0], aB + ks * 32);
            ldsm4(ah[1], aB + 2304 + ks * 32);
            #pragma unroll
            for (int nb = 0; nb < 4; nb++) {
                uint32_t bh[4];
                ldsm4(bh, bB + nb * 2304 + ks * 32);
                #pragma unroll
                for (int mt = 0; mt < 2; mt++)
                    #pragma unroll
                    for (int sub = 0; sub < 2; sub++)
                        mma_f16(acc[mt][nb * 2 + sub], ah[mt],
                                bh[sub*2], bh[sub*2+1]);
            }
        }
        __syncthreads();
    }

    float sums[2][2] = {{0.f,0.f},{0.f,0.f}}, sqs[2][2] = {{0.f,0.f},{0.f,0.f}};
    #pragma unroll
    for (int mt = 0; mt < 2; mt++) {
        int rl = r0 + m0 + mt * 16 + (lane >> 2);
        #pragma unroll
        for (int nt = 0; nt < 8; nt++) {
            int c = n0 + nt * 8 + (lane & 3) * 2;
            float2 bo2 = *(const float2*)(bop + c);
            float2 xl = ld2f(xres + (size_t)rl * 256 + c);
            float2 xh = ld2f(xres + (size_t)(rl + 8) * 256 + c);
            float4& a = acc[mt][nt];
            a.x += bo2.x + xl.x; a.y += bo2.y + xl.y;
            a.z += bo2.x + xh.x; a.w += bo2.y + xh.y;
            sums[mt][0] += a.x + a.y; sqs[mt][0] += a.x*a.x + a.y*a.y;
            sums[mt][1] += a.z + a.w; sqs[mt][1] += a.z*a.z + a.w*a.w;
        }
    }
    #pragma unroll
    for (int mt = 0; mt < 2; mt++)
        #pragma unroll
        for (int hf = 0; hf < 2; hf++) {
            sums[mt][hf] += __shfl_xor_sync(0xffffffffu, sums[mt][hf], 1);
            sums[mt][hf] += __shfl_xor_sync(0xffffffffu, sums[mt][hf], 2);
            sqs[mt][hf]  += __shfl_xor_sync(0xffffffffu, sqs[mt][hf], 1);
            sqs[mt][hf]  += __shfl_xor_sync(0xffffffffu, sqs[mt][hf], 2);
        }
    float* ssum = (float*)(sm + OLS_SUM);
    float* ssq  = (float*)(sm + OLS_SQ);
    if ((lane & 3) == 0) {
        #pragma unroll
        for (int mt = 0; mt < 2; mt++)
            #pragma unroll
            for (int hf = 0; hf < 2; hf++) {
                int row = m0 + mt * 16 + hf * 8 + (lane >> 2);
                ssum[(wid & 3) * 64 + row] = sums[mt][hf];
                ssq [(wid & 3) * 64 + row] = sqs[mt][hf];
            }
    }
    __syncthreads();
    float mu[2][2], rs[2][2];
    #pragma unroll
    for (int mt = 0; mt < 2; mt++)
        #pragma unroll
        for (int hf = 0; hf < 2; hf++) {
            int row = m0 + mt * 16 + hf * 8 + (lane >> 2);
            float s = ssum[row] + ssum[64 + row] + ssum[128 + row] + ssum[192 + row];
            float q = ssq[row] + ssq[64 + row] + ssq[128 + row] + ssq[192 + row];
            float m = s * (1.f / 256.f);
            mu[mt][hf] = m;
            rs[mt][hf] = rsqrtf(q * (1.f / 256.f) - m * m + 1e-5f);
        }
    #pragma unroll
    for (int mt = 0; mt < 2; mt++) {
        int rl = r0 + m0 + mt * 16 + (lane >> 2);
        #pragma unroll
        for (int nt = 0; nt < 8; nt++) {
            int c = n0 + nt * 8 + (lane & 3) * 2;
            float2 g2 = *(const float2*)(gp + c);
            float2 b2 = *(const float2*)(bbp + c);
            float4 a = acc[mt][nt];
            float2 o1, o2;
            o1.x = (a.x - mu[mt][0]) * rs[mt][0] * g2.x + b2.x;
            o1.y = (a.y - mu[mt][0]) * rs[mt][0] * g2.y + b2.y;
            o2.x = (a.z - mu[mt][1]) * rs[mt][1] * g2.x + b2.x;
            o2.y = (a.w - mu[mt][1]) * rs[mt][1] * g2.y + b2.y;
            st2f(out + (size_t)rl * 256 + c, o1);
            st2f(out + (size_t)(rl + 8) * 256 + c, o2);
        }
    }
}

// ================= attention common (fp16 input, fp32 smem/math) =================
#define ATT_STRIDE 288
#define ATT1_SMEM (WIN * ATT_STRIDE * 4)       // 50688 (QK==V)
#define ATT2_SMEM (2 * WIN * ATT_STRIDE * 4)   // 101376

__device__ __forceinline__ float4 h4_to_f4(uint2 raw) {
    __half2 h0 = *reinterpret_cast<__half2*>(&raw.x);
    __half2 h1 = *reinterpret_cast<__half2*>(&raw.y);
    return make_float4(__low2float(h0), __high2float(h0),
                       __low2float(h1), __high2float(h1));
}

__device__ __forceinline__ void attn_core(
    const float* sQK, const float* sV, int tid, int b, int s0,
    __half* __restrict__ ath, float* __restrict__ scores)
{
    const int sl = tid >> 3, h = tid & 7;
    const int dil = (h < 4) ? 3 : 1;
    const float scale = 0.1767766952966369f;  // 32^-0.5
    const int colb = h * 36;

    float4 q[8];
    {
        const float* qr = sQK + (sl + 6) * ATT_STRIDE + colb;
        #pragma unroll
        for (int j = 0; j < 8; j++) q[j] = *(const float4*)(qr + j * 4);
    }

    float sc[5];
    #pragma unroll
    for (int k = 0; k < 5; k++) {
        const float* kr = sQK + (sl + 6 + (k - 2) * dil) * ATT_STRIDE + colb;
        float d = 0.f;
        #pragma unroll
        for (int j = 0; j < 8; j++) {
            float4 kv = *(const float4*)(kr + j * 4);
            d += q[j].x * kv.x + q[j].y * kv.y + q[j].z * kv.z + q[j].w * kv.w;
        }
        sc[k] = d * scale;
    }
    float mx = sc[0];
    #pragma unroll
    for (int k = 1; k < 5; k++) mx = fmaxf(mx, sc[k]);
    float ex[5], sum = 0.f;
    #pragma unroll
    for (int k = 0; k < 5; k++) { ex[k] = __expf(sc[k] - mx); sum += ex[k]; }
    float inv = 1.f / sum;
    #pragma unroll
    for (int k = 0; k < 5; k++) ex[k] *= inv;

    size_t base = ((size_t)b * Ssz + s0 + sl) * 256 + h * 32;
    const float* v0 = sV + (sl + 6 - 2 * dil) * ATT_STRIDE + colb;
    const int vstep = dil * ATT_STRIDE;
    uint32_t Hw[16];
    #pragma unroll
    for (int j = 0; j < 8; j++) {
        float4 o = make_float4(0.f, 0.f, 0.f, 0.f);
        #pragma unroll
        for (int k = 0; k < 5; k++) {
            float4 vv = *(const float4*)(v0 + k * vstep + j * 4);
            o.x += ex[k] * vv.x; o.y += ex[k] * vv.y;
            o.z += ex[k] * vv.z; o.w += ex[k] * vv.w;
        }
        __half2 h0 = __floats2half2_rn(o.x, o.y);
        __half2 h1 = __floats2half2_rn(o.z, o.w);
        Hw[2*j]   = *reinterpret_cast<uint32_t*>(&h0);
        Hw[2*j+1] = *reinterpret_cast<uint32_t*>(&h1);
    }
    #pragma unroll
    for (int u = 0; u < 4; u++) {
        uint4 vh = make_uint4(Hw[u*4], Hw[u*4+1], Hw[u*4+2], Hw[u*4+3]);
        *(uint4*)((char*)(ath + base) + u * 16) = vh;
    }

    if (scores != nullptr) {
        float* sp = scores + (((size_t)b * 8 + h) * Ssz + s0 + sl) * 5;
        #pragma unroll
        for (int k = 0; k < 5; k++) sp[k] = ex[k];
    }
}

// attention, QK == V (blocks 1 & 2 batched via blockIdx.z)
__global__ __launch_bounds__(256) void attn_same(
    const __half* __restrict__ qk0, const __half* __restrict__ qk1,
    __half* __restrict__ ath0, __half* __restrict__ ath1,
    float* __restrict__ qs)
{
    extern __shared__ float smf[];
    const int chain = blockIdx.z;
    const __half* QK = chain ? qk1 : qk0;
    const int b  = blockIdx.y;
    const int s0 = blockIdx.x * 32;
    const int tid = threadIdx.x;

    for (int idx = tid; idx < WIN * 64; idx += 256) {
        int w = idx >> 6, c4 = idx & 63;
        int s = s0 + w - 6;
        float4 vq = make_float4(0.f, 0.f, 0.f, 0.f);
        if (s >= 0 && s < Ssz)
            vq = h4_to_f4(((const uint2*)QK)[((size_t)b * Ssz + s) * 64 + c4]);
        *(float4*)(smf + w * ATT_STRIDE + (c4 >> 3) * 36 + (c4 & 7) * 4) = vq;
    }
    __syncthreads();

    attn_core(smf, smf, tid, b, s0, chain ? ath1 : ath0, chain ? qs : nullptr);
}

// attention, QK != V (block 3)
__global__ __launch_bounds__(256) void attn_two(
    const __half* __restrict__ QK, const __half* __restrict__ V,
    __half* __restrict__ ath)
{
    extern __shared__ float smf[];
    float* sQK = smf;
    float* sV  = smf + WIN * ATT_STRIDE;
    const int b  = blockIdx.y;
    const int s0 = blockIdx.x * 32;
    const int tid = threadIdx.x;

    for (int idx = tid; idx < WIN * 64; idx += 256) {
        int w = idx >> 6, c4 = idx & 63;
        int s = s0 + w - 6;
        float4 vq = make_float4(0.f, 0.f, 0.f, 0.f);
        float4 vv = vq;
        if (s >= 0 && s < Ssz) {
            size_t off = ((size_t)b * Ssz + s) * 64 + c4;
            vq = h4_to_f4(((const uint2*)QK)[off]);
            vv = h4_to_f4(((const uint2*)V)[off]);
        }
        int sc = w * ATT_STRIDE + (c4 >> 3) * 36 + (c4 & 7) * 4;
        *(float4*)(sQK + sc) = vq;
        *(float4*)(sV + sc)  = vv;
    }
    __syncthreads();

    attn_core(sQK, sV, tid, b, s0, ath, nullptr);
}

// ================= launch =================
extern "C" void kernel_launch(void* const* d_in, const int* in_sizes, int n_in,
                              void* d_out, int out_size)
{
    (void)in_sizes; (void)n_in; (void)out_size;
    const float* q_emb = (const float*)d_in[0];
    const float* s_emb = (const float*)d_in[1];
    const float* W_lin = (const float*)d_in[3];  // (3,2,128,128)
    const float* b_lin = (const float*)d_in[4];  // (3,2,128)
    const float* W_out = (const float*)d_in[5];  // (3,256,256)
    const float* b_out = (const float*)d_in[6];  // (3,256)
    const float* ln_g  = (const float*)d_in[7];  // (3,256)
    const float* ln_b  = (const float*)d_in[8];  // (3,256)

    float* outp = (float*)d_out;
    float* z  = outp;
    float* qs = outp + (size_t)BS * 256;

    __half *p_qk0, *p_qk1, *p_v, *p_hq, *p_hs, *p_ath0, *p_ath1, *p_wlh, *p_woh;
    cudaGetSymbolAddress((void**)&p_qk0, g_qk0);
    cudaGetSymbolAddress((void**)&p_qk1, g_qk1);
    cudaGetSymbolAddress((void**)&p_v,   g_v);
    cudaGetSymbolAddress((void**)&p_hq,  g_hq);
    cudaGetSymbolAddress((void**)&p_hs,  g_hs);
    cudaGetSymbolAddress((void**)&p_ath0, g_ath0);
    cudaGetSymbolAddress((void**)&p_ath1, g_ath1);
    cudaGetSymbolAddress((void**)&p_wlh, g_wlh);
    cudaGetSymbolAddress((void**)&p_woh, g_woh);

    const int smemP  = (int)PR_SMEM;    // 52736
    const int smemO  = (int)OLS_SMEM;   // 94208
    const int smemA1 = ATT1_SMEM;
    const int smemA2 = ATT2_SMEM;
    cudaFuncSetAttribute(proj_mma<float>,  cudaFuncAttributeMaxDynamicSharedMemorySize, smemP);
    cudaFuncSetAttribute(proj_mma<__half>, cudaFuncAttributeMaxDynamicSharedMemorySize, smemP);
    cudaFuncSetAttribute((const void*)outln_mma<float, __half>,
                         cudaFuncAttributeMaxDynamicSharedMemorySize, smemO);
    cudaFuncSetAttribute((const void*)outln_mma<__half, float>,
                         cudaFuncAttributeMaxDynamicSharedMemorySize, smemO);
    cudaFuncSetAttribute(attn_same, cudaFuncAttributeMaxDynamicSharedMemorySize, smemA1);
    cudaFuncSetAttribute(attn_two,  cudaFuncAttributeMaxDynamicSharedMemorySize, smemA2);

    split_w<<<768, 256>>>(W_lin, W_out, p_wlh, p_woh);

    // ---- blocks 1 & 2, batched ----
    proj_mma<float><<<dim3(BS/64, 2, 2), 256, smemP>>>(
        q_emb, s_emb, p_wlh, 32768, b_lin, 256, p_qk0, p_qk1);
    attn_same<<<dim3(Ssz/32, Bsz, 2), 256, smemA1>>>(
        p_qk0, p_qk1, p_ath0, p_ath1, qs);
    outln_mma<float, __half><<<dim3(BS/64, 2), 256, smemO>>>(
        p_ath0, p_ath1, p_woh, 65536,
        b_out, q_emb, s_emb, ln_g, ln_b, 256, p_hq, p_hs);

    // ---- block 3 ----
    proj_mma<__half><<<dim3(BS/64, 2, 2), 256, smemP>>>(
        p_hq, p_hs, p_wlh + 65536, 0, b_lin + 512, 0, p_qk0, p_v);
    attn_two<<<dim3(Ssz/32, Bsz), 256, smemA2>>>(p_qk0, p_v, p_ath0);
    outln_mma<__half, float><<<dim3(BS/64, 1), 256, smemO>>>(
        p_ath0, p_ath0, p_woh + 131072, 0,
        b_out + 512, p_hq, p_hq, ln_g + 512, ln_b + 512, 0, z, z);
}

// round 17
// speedup vs baseline: 1.1783x; 1.0010x over previous
#include <cuda_runtime.h>
#include <cuda_fp16.h>
#include <cstdint>

#define Bsz 32
#define Ssz 2048
#define BS (Bsz*Ssz)   // 65536 rows

// ---------------- scratch (device globals; no allocation) ----------------
__device__ __half g_qk0[(size_t)BS*256];
__device__ __half g_qk1[(size_t)BS*256];
__device__ __half g_v  [(size_t)BS*256];
__device__ __half g_hq [(size_t)BS*256];
__device__ __half g_hs [(size_t)BS*256];
__device__ __half g_ath0[(size_t)BS*256];
__device__ __half g_ath1[(size_t)BS*256];
__device__ __half g_wlh[3*2*128*128];
__device__ __half g_woh[3*256*256];

// ================= helpers =================
__device__ __forceinline__ uint32_t smem_u32(const void* p) {
    uint32_t a;
    asm("{ .reg .u64 t; cvta.to.shared.u64 t, %1; cvt.u32.u64 %0, t; }"
        : "=r"(a) : "l"(p));
    return a;
}
__device__ __forceinline__ void ldsm4(uint32_t r[4], uint32_t addr) {
    asm volatile("ldmatrix.sync.aligned.m8n8.x4.shared.b16 {%0,%1,%2,%3}, [%4];"
                 : "=r"(r[0]), "=r"(r[1]), "=r"(r[2]), "=r"(r[3]) : "r"(addr));
}
__device__ __forceinline__ void mma_f16(float4& c, const uint32_t a[4],
                                        uint32_t b0, uint32_t b1) {
    asm volatile(
        "mma.sync.aligned.m16n8k16.row.col.f32.f16.f16.f32 "
        "{%0,%1,%2,%3}, {%4,%5,%6,%7}, {%8,%9}, {%0,%1,%2,%3};"
        : "+f"(c.x), "+f"(c.y), "+f"(c.z), "+f"(c.w)
        : "r"(a[0]), "r"(a[1]), "r"(a[2]), "r"(a[3]), "r"(b0), "r"(b1));
}
__device__ __forceinline__ void cp16(uint32_t dst, const void* src) {
    asm volatile("cp.async.cg.shared.global [%0], [%1], 16;"
                 :: "r"(dst), "l"(src) : "memory");
}
__device__ __forceinline__ float2 ld2f(const float* p) { return *(const float2*)p; }
__device__ __forceinline__ float2 ld2f(const __half* p) {
    uint32_t r = *(const uint32_t*)p;
    __half2 h = *reinterpret_cast<__half2*>(&r);
    return make_float2(__low2float(h), __high2float(h));
}
__device__ __forceinline__ void st2f(float* p, float2 v) { *(float2*)p = v; }
__device__ __forceinline__ void st2f(__half* p, float2 v) {
    __half2 h = __floats2half2_rn(v.x, v.y);
    *(uint32_t*)p = *reinterpret_cast<uint32_t*>(&h);
}

// ================= weight fp16 prep =================
__global__ void split_w(const float* __restrict__ Wl, const float* __restrict__ Wo,
                        __half* __restrict__ wlh, __half* __restrict__ woh)
{
    int i = blockIdx.x * 256 + threadIdx.x;
    if (i < 3*2*128*128) wlh[i] = __float2half_rn(Wl[i]);
    if (i < 3*256*256)   woh[i] = __float2half_rn(Wo[i]);
}

// ================= projection GEMM v2 (R16 passing) =================
#define PR_A    0u
#define PR_W    17408u
#define PR_BIAS 52224u
#define PR_SMEM 52736u

__device__ __forceinline__ void fillA(const float* __restrict__ src,
                                      uint32_t* __restrict__ A, int tid) {
    #pragma unroll
    for (int it = 0; it < 16; it++) {
        int idx = tid + it * 256;
        int row = idx >> 6, c2 = idx & 63;
        float2 v = *(const float2*)(src + (size_t)row * 256 + c2 * 2);
        __half2 h = __floats2half2_rn(v.x, v.y);
        A[row * 68 + c2] = *reinterpret_cast<uint32_t*>(&h);
    }
}
__device__ __forceinline__ void fillA(const __half* __restrict__ src,
                                      uint32_t* __restrict__ A, int tid) {
    const uint32_t* s32 = (const uint32_t*)src;
    #pragma unroll
    for (int it = 0; it < 16; it++) {
        int idx = tid + it * 256;
        int row = idx >> 6, c2 = idx & 63;
        A[row * 68 + c2] = s32[(size_t)row * 128 + c2];
    }
}

template<typename TIN>
__global__ __launch_bounds__(256) void proj_mma(
    const TIN* __restrict__ x0, const TIN* __restrict__ x1,
    const __half* __restrict__ whi, int wstep,
    const float* __restrict__ bias, int bstep,
    __half* __restrict__ out0, __half* __restrict__ out1)
{
    extern __shared__ __align__(16) char sm[];
    uint32_t* Ahi = (uint32_t*)(sm + PR_A);
    float* sbias  = (float*)(sm + PR_BIAS);
    float* stg    = (float*)sm;

    const int chain = blockIdx.z;
    const TIN* x = chain ? x1 : x0;
    __half* out = chain ? out1 : out0;
    const int branch = blockIdx.y;
    const int r0 = blockIdx.x * 64;
    const int tid = threadIdx.x, lane = tid & 31, wid = tid >> 5;
    const int m0 = (wid >> 2) * 32, n0 = (wid & 3) * 32;
    const uint32_t sb = smem_u32(sm);
    const uint32_t sA = sb + PR_A, sW = sb + PR_W;

    {
        const __half* wsrc = whi + (size_t)chain * wstep + (size_t)branch * 128 * 128;
        #pragma unroll
        for (int it = 0; it < 8; it++) {
            int idx = tid + it * 256;
            int row = idx >> 4, u = idx & 15;
            cp16(sW + row * 272 + u * 16, wsrc + (size_t)row * 128 + u * 8);
        }
        asm volatile("cp.async.commit_group;" ::: "memory");
    }
    if (tid < 128) sbias[tid] = bias[chain * bstep + branch * 128 + tid];

    fillA(x + (size_t)r0 * 256 + branch * 128, Ahi, tid);

    asm volatile("cp.async.wait_group 0;" ::: "memory");
    __syncthreads();

    const int a_row = lane & 15, a_kh = (lane >> 4) << 3;
    const int b_n = (lane & 7) + ((lane >> 4) << 3);
    const int b_kh = ((lane >> 3) & 1) << 3;
    uint32_t aAddr[2], bAddr[2];
    aAddr[0] = sA + ((m0 + a_row) * 136 + a_kh) * 2;
    aAddr[1] = sA + ((m0 + 16 + a_row) * 136 + a_kh) * 2;
    bAddr[0] = sW + ((n0 + b_n) * 136 + b_kh) * 2;
    bAddr[1] = sW + ((n0 + 16 + b_n) * 136 + b_kh) * 2;

    float4 acc[2][4];
    #pragma unroll
    for (int i = 0; i < 2; i++)
        #pragma unroll
        for (int j = 0; j < 4; j++) acc[i][j] = make_float4(0.f, 0.f, 0.f, 0.f);

    #pragma unroll
    for (int ks = 0; ks < 8; ks++) {
        uint32_t ah[2][4], bh[2][4];
        #pragma unroll
        for (int mt = 0; mt < 2; mt++) ldsm4(ah[mt], aAddr[mt] + ks * 32);
        #pragma unroll
        for (int bt = 0; bt < 2; bt++) ldsm4(bh[bt], bAddr[bt] + ks * 32);
        #pragma unroll
        for (int mt = 0; mt < 2; mt++)
            #pragma unroll
            for (int bt = 0; bt < 2; bt++)
                #pragma unroll
                for (int sub = 0; sub < 2; sub++)
                    mma_f16(acc[mt][bt * 2 + sub], ah[mt],
                            bh[bt][sub*2], bh[bt][sub*2+1]);
    }
    __syncthreads();

    #pragma unroll
    for (int mt = 0; mt < 2; mt++) {
        int rb = m0 + mt * 16 + (lane >> 2);
        #pragma unroll
        for (int nt = 0; nt < 4; nt++) {
            int j = n0 + nt * 8 + (lane & 3) * 2;
            int p0 = ((j & 31) << 2) + (j >> 5);
            int p1 = (((j + 1) & 31) << 2) + ((j + 1) >> 5);
            float4 a = acc[mt][nt];
            stg[rb * 132 + p0]       = a.x + sbias[j];
            stg[rb * 132 + p1]       = a.y + sbias[j + 1];
            stg[(rb + 8) * 132 + p0] = a.z + sbias[j];
            stg[(rb + 8) * 132 + p1] = a.w + sbias[j + 1];
        }
    }
    __syncthreads();
    #pragma unroll
    for (int it = 0; it < 8; it++) {
        int idx = tid + it * 256;
        int row = idx >> 5, q = idx & 31;
        float4 v = *(const float4*)(stg + row * 132 + q * 4);
        __half2 h0 = __floats2half2_rn(v.x, v.y);
        __half2 h1 = __floats2half2_rn(v.z, v.w);
        uint2 u = make_uint2(*reinterpret_cast<uint32_t*>(&h0),
                             *reinterpret_cast<uint32_t*>(&h1));
        *(uint2*)(out + (size_t)(r0 + row) * 256 + branch * 128 + q * 4) = u;
    }
}

// ================= out-proj + bias + residual + LN (K=32, 4-stage pipeline) =================
// stage = A 64x32 (5120 B, stride 40h) + W 256x32 (20480 B, stride 40h) = 25600 B x4.
#define OLS_STAGE 25600u
#define OLS_SUM   102400u
#define OLS_SQ    103424u
#define OLS_SMEM  104448u

template<typename TX, typename TO>
__global__ __launch_bounds__(256) void outln_mma(
    const __half* __restrict__ A0h, const __half* __restrict__ A1h,
    const __half* __restrict__ Whi, int wstep,
    const float* __restrict__ bo, const TX* __restrict__ xr0,
    const TX* __restrict__ xr1,
    const float* __restrict__ g, const float* __restrict__ bb, int pstep,
    TO* __restrict__ out0, TO* __restrict__ out1)
{
    extern __shared__ __align__(16) char sm[];
    const int chain = blockIdx.y;
    const __half* Ahi = chain ? A1h : A0h;
    const __half* Wp  = Whi + (size_t)chain * wstep;
    const TX* xres = chain ? xr1 : xr0;
    const float* bop = bo + chain * pstep;
    const float* gp  = g  + chain * pstep;
    const float* bbp = bb + chain * pstep;
    TO* out = chain ? out1 : out0;

    const int r0 = blockIdx.x * 64;
    const int tid = threadIdx.x, lane = tid & 31, wid = tid >> 5;
    const int m0 = (wid >> 2) * 32, n0 = (wid & 3) * 64;
    const uint32_t sb = smem_u32(sm);

    auto load_chunk = [&](int kc) {
        uint32_t st = sb + (uint32_t)(kc & 3) * OLS_STAGE;
        const __half* ah = Ahi + (size_t)r0 * 256 + kc * 32;
        const __half* wh = Wp + kc * 32;
        {   // A: 64 rows x 4 quads
            int row = tid >> 2, u = tid & 3;
            cp16(st + row * 80 + u * 16, ah + (size_t)row * 256 + u * 8);
        }
        #pragma unroll
        for (int it = 0; it < 4; it++) {   // W: 256 rows x 4 quads
            int idx = tid + it * 256;
            int row = idx >> 2, u = idx & 3;
            cp16(st + 5120u + row * 80 + u * 16, wh + (size_t)row * 256 + u * 8);
        }
        asm volatile("cp.async.commit_group;" ::: "memory");
    };

    const int a_row = lane & 15, a_kh = (lane >> 4) << 3;
    const int b_n = (lane & 7) + ((lane >> 4) << 3);
    const int b_kh = ((lane >> 3) & 1) << 3;
    const uint32_t aOff = ((m0 + a_row) * 40 + a_kh) * 2;
    const uint32_t bOff = 5120u + ((n0 + b_n) * 40 + b_kh) * 2;

    float4 acc[2][8];
    #pragma unroll
    for (int i = 0; i < 2; i++)
        #pragma unroll
        for (int j = 0; j < 8; j++) acc[i][j] = make_float4(0.f, 0.f, 0.f, 0.f);

    load_chunk(0); load_chunk(1); load_chunk(2); load_chunk(3);

    #pragma unroll 1
    for (int kc = 0; kc < 8; kc++) {
        if (kc < 5)      asm volatile("cp.async.wait_group 3;" ::: "memory");
        else if (kc == 5) asm volatile("cp.async.wait_group 2;" ::: "memory");
        else if (kc == 6) asm volatile("cp.async.wait_group 1;" ::: "memory");
        else              asm volatile("cp.async.wait_group 0;" ::: "memory");
        __syncthreads();
        uint32_t st = sb + (uint32_t)(kc & 3) * OLS_STAGE;
        uint32_t aB = st + aOff, bB = st + bOff;
        #pragma unroll
        for (int ks = 0; ks < 2; ks++) {
            uint32_t ah[2][4];
            ldsm4(ah[0], aB + ks * 32);
            ldsm4(ah[1], aB + 1280 + ks * 32);
            #pragma unroll
            for (int nb = 0; nb < 4; nb++) {
                uint32_t bh[4];
                ldsm4(bh, bB + nb * 1280 + ks * 32);
                #pragma unroll
                for (int mt = 0; mt < 2; mt++)
                    #pragma unroll
                    for (int sub = 0; sub < 2; sub++)
                        mma_f16(acc[mt][nb * 2 + sub], ah[mt],
                                bh[sub*2], bh[sub*2+1]);
            }
        }
        __syncthreads();
        if (kc < 4) load_chunk(kc + 4);
    }

    float sums[2][2] = {{0.f,0.f},{0.f,0.f}}, sqs[2][2] = {{0.f,0.f},{0.f,0.f}};
    #pragma unroll
    for (int mt = 0; mt < 2; mt++) {
        int rl = r0 + m0 + mt * 16 + (lane >> 2);
        #pragma unroll
        for (int nt = 0; nt < 8; nt++) {
            int c = n0 + nt * 8 + (lane & 3) * 2;
            float2 bo2 = *(const float2*)(bop + c);
            float2 xl = ld2f(xres + (size_t)rl * 256 + c);
            float2 xh = ld2f(xres + (size_t)(rl + 8) * 256 + c);
            float4& a = acc[mt][nt];
            a.x += bo2.x + xl.x; a.y += bo2.y + xl.y;
            a.z += bo2.x + xh.x; a.w += bo2.y + xh.y;
            sums[mt][0] += a.x + a.y; sqs[mt][0] += a.x*a.x + a.y*a.y;
            sums[mt][1] += a.z + a.w; sqs[mt][1] += a.z*a.z + a.w*a.w;
        }
    }
    #pragma unroll
    for (int mt = 0; mt < 2; mt++)
        #pragma unroll
        for (int hf = 0; hf < 2; hf++) {
            sums[mt][hf] += __shfl_xor_sync(0xffffffffu, sums[mt][hf], 1);
            sums[mt][hf] += __shfl_xor_sync(0xffffffffu, sums[mt][hf], 2);
            sqs[mt][hf]  += __shfl_xor_sync(0xffffffffu, sqs[mt][hf], 1);
            sqs[mt][hf]  += __shfl_xor_sync(0xffffffffu, sqs[mt][hf], 2);
        }
    float* ssum = (float*)(sm + OLS_SUM);
    float* ssq  = (float*)(sm + OLS_SQ);
    if ((lane & 3) == 0) {
        #pragma unroll
        for (int mt = 0; mt < 2; mt++)
            #pragma unroll
            for (int hf = 0; hf < 2; hf++) {
                int row = m0 + mt * 16 + hf * 8 + (lane >> 2);
                ssum[(wid & 3) * 64 + row] = sums[mt][hf];
                ssq [(wid & 3) * 64 + row] = sqs[mt][hf];
            }
    }
    __syncthreads();
    float mu[2][2], rs[2][2];
    #pragma unroll
    for (int mt = 0; mt < 2; mt++)
        #pragma unroll
        for (int hf = 0; hf < 2; hf++) {
            int row = m0 + mt * 16 + hf * 8 + (lane >> 2);
            float s = ssum[row] + ssum[64 + row] + ssum[128 + row] + ssum[192 + row];
            float q = ssq[row] + ssq[64 + row] + ssq[128 + row] + ssq[192 + row];
            float m = s * (1.f / 256.f);
            mu[mt][hf] = m;
            rs[mt][hf] = rsqrtf(q * (1.f / 256.f) - m * m + 1e-5f);
        }
    #pragma unroll
    for (int mt = 0; mt < 2; mt++) {
        int rl = r0 + m0 + mt * 16 + (lane >> 2);
        #pragma unroll
        for (int nt = 0; nt < 8; nt++) {
            int c = n0 + nt * 8 + (lane & 3) * 2;
            float2 g2 = *(const float2*)(gp + c);
            float2 b2 = *(const float2*)(bbp + c);
            float4 a = acc[mt][nt];
            float2 o1, o2;
            o1.x = (a.x - mu[mt][0]) * rs[mt][0] * g2.x + b2.x;
            o1.y = (a.y - mu[mt][0]) * rs[mt][0] * g2.y + b2.y;
            o2.x = (a.z - mu[mt][1]) * rs[mt][1] * g2.x + b2.x;
            o2.y = (a.w - mu[mt][1]) * rs[mt][1] * g2.y + b2.y;
            st2f(out + (size_t)rl * 256 + c, o1);
            st2f(out + (size_t)(rl + 8) * 256 + c, o2);
        }
    }
}

// ================= attention: fp16 skewed smem (proven R13/R14 layout) =================
// window 44 rows x 128 fp16-pairs; row stride 136 u32, head stride 17.
#define ATTH1_SMEM (44 * 136 * 4)       // 23936 -> up to 8 CTA/SM
#define ATTH2_SMEM (2 * 44 * 136 * 4)   // 47872 -> 4 CTA/SM

__device__ __forceinline__ void attn_core_h(
    const uint32_t* sQK, const uint32_t* sV, int tid, int b, int s0,
    __half* __restrict__ ath, float* __restrict__ scores)
{
    const int sl = tid >> 3, h = tid & 7;
    const int dil = (h < 4) ? 3 : 1;
    const float scale = 0.1767766952966369f;  // 32^-0.5
    const uint32_t* qp = sQK + (sl + 6) * 136 + h * 17;

    float qv[32];
    #pragma unroll
    for (int j = 0; j < 16; j++) {
        __half2 hh = *(const __half2*)(qp + j);
        qv[2*j] = __low2float(hh); qv[2*j+1] = __high2float(hh);
    }
    float sc[5];
    #pragma unroll
    for (int k = 0; k < 5; k++) {
        const uint32_t* kp = sQK + (sl + 6 + (k - 2) * dil) * 136 + h * 17;
        float d = 0.f;
        #pragma unroll
        for (int j = 0; j < 16; j++) {
            __half2 kh = *(const __half2*)(kp + j);
            d += qv[2*j] * __low2float(kh) + qv[2*j+1] * __high2float(kh);
        }
        sc[k] = d * scale;
    }
    float mx = sc[0];
    #pragma unroll
    for (int k = 1; k < 5; k++) mx = fmaxf(mx, sc[k]);
    float ex[5], sum = 0.f;
    #pragma unroll
    for (int k = 0; k < 5; k++) { ex[k] = __expf(sc[k] - mx); sum += ex[k]; }
    float inv = 1.f / sum;
    #pragma unroll
    for (int k = 0; k < 5; k++) ex[k] *= inv;

    size_t base = ((size_t)b * Ssz + s0 + sl) * 256 + h * 32;
    const uint32_t* v0 = sV + (sl + 6 - 2 * dil) * 136 + h * 17;
    const int vstep = dil * 136;
    uint32_t Hw[16];
    #pragma unroll
    for (int j = 0; j < 16; j++) {
        float ox = 0.f, oy = 0.f;
        #pragma unroll
        for (int k = 0; k < 5; k++) {
            __half2 vh = *(const __half2*)(v0 + k * vstep + j);
            ox += ex[k] * __low2float(vh);
            oy += ex[k] * __high2float(vh);
        }
        __half2 oh = __floats2half2_rn(ox, oy);
        Hw[j] = *reinterpret_cast<uint32_t*>(&oh);
    }
    #pragma unroll
    for (int u = 0; u < 4; u++) {
        uint4 vh = make_uint4(Hw[u*4], Hw[u*4+1], Hw[u*4+2], Hw[u*4+3]);
        *(uint4*)((char*)(ath + base) + u * 16) = vh;
    }

    if (scores != nullptr) {
        float* sp = scores + (((size_t)b * 8 + h) * Ssz + s0 + sl) * 5;
        #pragma unroll
        for (int k = 0; k < 5; k++) sp[k] = ex[k];
    }
}

// attention, QK == V (blocks 1 & 2 batched via blockIdx.z)
__global__ __launch_bounds__(256) void attn_same(
    const __half* __restrict__ qk0, const __half* __restrict__ qk1,
    __half* __restrict__ ath0, __half* __restrict__ ath1,
    float* __restrict__ qs)
{
    extern __shared__ uint32_t smu[];
    const int chain = blockIdx.z;
    const __half* QK = chain ? qk1 : qk0;
    const int b  = blockIdx.y;
    const int s0 = blockIdx.x * 32;
    const int tid = threadIdx.x;

    for (int idx = tid; idx < 44 * 128; idx += 256) {
        int w = idx >> 7, p = idx & 127;
        int s = s0 + w - 6;
        uint32_t v = 0;
        if (s >= 0 && s < Ssz)
            v = ((const uint32_t*)QK)[((size_t)b * Ssz + s) * 128 + p];
        smu[w * 136 + (p >> 4) * 17 + (p & 15)] = v;
    }
    __syncthreads();

    attn_core_h(smu, smu, tid, b, s0, chain ? ath1 : ath0, chain ? qs : nullptr);
}

// attention, QK != V (block 3)
__global__ __launch_bounds__(256) void attn_two(
    const __half* __restrict__ QK, const __half* __restrict__ V,
    __half* __restrict__ ath)
{
    extern __shared__ uint32_t smu[];
    uint32_t* sQK = smu;
    uint32_t* sV  = smu + 44 * 136;
    const int b  = blockIdx.y;
    const int s0 = blockIdx.x * 32;
    const int tid = threadIdx.x;

    for (int idx = tid; idx < 44 * 128; idx += 256) {
        int w = idx >> 7, p = idx & 127;
        int s = s0 + w - 6;
        uint32_t vq = 0, vv = 0;
        if (s >= 0 && s < Ssz) {
            size_t off = ((size_t)b * Ssz + s) * 128 + p;
            vq = ((const uint32_t*)QK)[off];
            vv = ((const uint32_t*)V)[off];
        }
        int sc = w * 136 + (p >> 4) * 17 + (p & 15);
        sQK[sc] = vq;
        sV[sc]  = vv;
    }
    __syncthreads();

    attn_core_h(sQK, sV, tid, b, s0, ath, nullptr);
}

// ================= launch =================
extern "C" void kernel_launch(void* const* d_in, const int* in_sizes, int n_in,
                              void* d_out, int out_size)
{
    (void)in_sizes; (void)n_in; (void)out_size;
    const float* q_emb = (const float*)d_in[0];
    const float* s_emb = (const float*)d_in[1];
    const float* W_lin = (const float*)d_in[3];  // (3,2,128,128)
    const float* b_lin = (const float*)d_in[4];  // (3,2,128)
    const float* W_out = (const float*)d_in[5];  // (3,256,256)
    const float* b_out = (const float*)d_in[6];  // (3,256)
    const float* ln_g  = (const float*)d_in[7];  // (3,256)
    const float* ln_b  = (const float*)d_in[8];  // (3,256)

    float* outp = (float*)d_out;
    float* z  = outp;
    float* qs = outp + (size_t)BS * 256;

    __half *p_qk0, *p_qk1, *p_v, *p_hq, *p_hs, *p_ath0, *p_ath1, *p_wlh, *p_woh;
    cudaGetSymbolAddress((void**)&p_qk0, g_qk0);
    cudaGetSymbolAddress((void**)&p_qk1, g_qk1);
    cudaGetSymbolAddress((void**)&p_v,   g_v);
    cudaGetSymbolAddress((void**)&p_hq,  g_hq);
    cudaGetSymbolAddress((void**)&p_hs,  g_hs);
    cudaGetSymbolAddress((void**)&p_ath0, g_ath0);
    cudaGetSymbolAddress((void**)&p_ath1, g_ath1);
    cudaGetSymbolAddress((void**)&p_wlh, g_wlh);
    cudaGetSymbolAddress((void**)&p_woh, g_woh);

    const int smemP  = (int)PR_SMEM;    // 52736
    const int smemO  = (int)OLS_SMEM;   // 104448
    const int smemA1 = ATTH1_SMEM;      // 23936
    const int smemA2 = ATTH2_SMEM;      // 47872
    cudaFuncSetAttribute(proj_mma<float>,  cudaFuncAttributeMaxDynamicSharedMemorySize, smemP);
    cudaFuncSetAttribute(proj_mma<__half>, cudaFuncAttributeMaxDynamicSharedMemorySize, smemP);
    cudaFuncSetAttribute((const void*)outln_mma<float, __half>,
                         cudaFuncAttributeMaxDynamicSharedMemorySize, smemO);
    cudaFuncSetAttribute((const void*)outln_mma<__half, float>,
                         cudaFuncAttributeMaxDynamicSharedMemorySize, smemO);
    cudaFuncSetAttribute(attn_same, cudaFuncAttributeMaxDynamicSharedMemorySize, smemA1);
    cudaFuncSetAttribute(attn_two,  cudaFuncAttributeMaxDynamicSharedMemorySize, smemA2);

    split_w<<<768, 256>>>(W_lin, W_out, p_wlh, p_woh);

    // ---- blocks 1 & 2, batched ----
    proj_mma<float><<<dim3(BS/64, 2, 2), 256, smemP>>>(
        q_emb, s_emb, p_wlh, 32768, b_lin, 256, p_qk0, p_qk1);
    attn_same<<<dim3(Ssz/32, Bsz, 2), 256, smemA1>>>(
        p_qk0, p_qk1, p_ath0, p_ath1, qs);
    outln_mma<float, __half><<<dim3(BS/64, 2), 256, smemO>>>(
        p_ath0, p_ath1, p_woh, 65536,
        b_out, q_emb, s_emb, ln_g, ln_b, 256, p_hq, p_hs);

    // ---- block 3 ----
    proj_mma<__half><<<dim3(BS/64, 2, 2), 256, smemP>>>(
        p_hq, p_hs, p_wlh + 65536, 0, b_lin + 512, 0, p_qk0, p_v);
    attn_two<<<dim3(Ssz/32, Bsz), 256, smemA2>>>(p_qk0, p_v, p_ath0);
    outln_mma<__half, float><<<dim3(BS/64, 1), 256, smemO>>>(
        p_ath0, p_ath0, p_woh + 131072, 0,
        b_out + 512, p_hq, p_hq, ln_g + 512, ln_b + 512, 0, z, z);
}